// round 4
// baseline (speedup 1.0000x reference)
#include <cuda_runtime.h>
#include <cstdint>

#define HW    512
#define NPIX  (HW*HW)        // 262144 = 2^18
#define BATCH 8
#define NBINS 9
#define CELLS 32

static __device__ float  g_gray[BATCH*NPIX];          // 8 MB
static __device__ float4 g_pix [BATCH*NPIX];          // 32 MB  (w0, w1, slot*297 as int bits, 0)
static __device__ float  g_hog [BATCH*CELLS*CELLS*NBINS];
static __device__ float  g_qv  [BATCH*2*CELLS*CELLS]; // quantized dominant dir (as float)
static __device__ float  g_tmp [BATCH*2*HW*CELLS];    // H-resized intermediate [bc][512][32]
static __device__ float  g_filt[33*33];               // radial tent filter
static __device__ float4 g_rwp [HW*2];                // packed lanczos weights: w0..w5, j0(bits), 0

__device__ __forceinline__ float lanczos3(float x) {
    // matches jax _fill_lanczos_kernel(radius=3) in f32
    if (x > 3.0f) return 0.0f;
    if (x > 1e-3f) {
        float px = 3.1415927410125732f * x;
        float y  = (3.0f * sinf(px)) * sinf(px / 3.0f);
        return y / (9.8696044921875f * (x * x));   // np.pi**2 -> f32
    }
    return 1.0f;
}

// ---------------- init: filter table + lanczos resize weights ----------------
__global__ void k_init() {
    int t = blockIdx.x * blockDim.x + threadIdx.x;
    if (t < 1089) {
        int dy = t / 33 - 16, dx = t % 33 - 16;
        float dist = sqrtf((float)(dy*dy + dx*dx));
        // reference: (1.0 - dist_f32 / (16*math.sqrt(2.0))) computed in double, cast f32
        g_filt[t] = (float)(1.0 - (double)dist / 22.627416997969522);
    }
    if (t < HW) {
        float sample = (t + 0.5f) * 0.0625f - 0.5f;
        int j0 = (int)floorf(sample - 3.0f) + 1;
        float w[6]; float wsum = 0.0f;
        #pragma unroll
        for (int k = 0; k < 6; k++) {
            int j = j0 + k;
            float wt = 0.0f;
            if (j >= 0 && j < 32) wt = lanczos3(fabsf(sample - (float)j));
            w[k] = wt; wsum += wt;
        }
        float4 a, b;
        a.x = w[0]/wsum; a.y = w[1]/wsum; a.z = w[2]/wsum; a.w = w[3]/wsum;
        b.x = w[4]/wsum; b.y = w[5]/wsum; b.z = __int_as_float(j0); b.w = 0.0f;
        g_rwp[t*2]   = a;
        g_rwp[t*2+1] = b;
    }
}

// ---------------- grayscale ----------------
__global__ void k_gray(const float* __restrict__ x) {
    int i = blockIdx.x * blockDim.x + threadIdx.x;   // BATCH*NPIX
    int b = i >> 18;
    int p = i & (NPIX - 1);
    const float* xb = x + (size_t)b * 3 * NPIX;
    g_gray[i] = xb[p]*0.299f + xb[NPIX+p]*0.587f + xb[2*NPIX+p]*0.114f;
}

// ---------------- gradient -> magnitude + 2-bin decomposition ----------------
__global__ void k_grad() {
    int i = blockIdx.x * blockDim.x + threadIdx.x;
    int b = i >> 18;
    int p = i & (NPIX - 1);
    int r = p >> 9, c = p & 511;
    const float* gb = g_gray + b * NPIX;
    float gl = (c > 0)   ? gb[p-1]   : 0.0f;
    float gr = (c < 511) ? gb[p+1]   : 0.0f;
    float gu = (r > 0)   ? gb[p-512] : 0.0f;
    float gd = (r < 511) ? gb[p+512] : 0.0f;
    float gx = gr - gl;
    float gy = gd - gu;
    float mag = sqrtf(gx*gx + gy*gy);
    const float PI_F = 3.1415927410125732f;
    float t  = atan2f(gy, gx) + PI_F;          // (0, 2pi]
    float o  = fmodf(t, PI_F);                 // jnp.mod for x>=0, y>0
    float orient = (o / PI_F) * 180.0f;
    float ob = orient * 0.05f;                 // orientation in bin units, in [0, 9]
    float f  = ob - 0.5f;
    float fb = floorf(f);
    int   b0 = (int)fb;                        // -1..8
    float frac = f - fb;
    float4 v;
    v.x = mag * (1.0f - frac);                 // weight for bin b0
    v.y = mag * frac;                          // weight for bin b0+1
    v.z = __int_as_float((b0 + 1) * 297);      // shared-mem row offset (slot in [0,10])
    v.w = 0.0f;
    g_pix[i] = v;
}

// ---------------- HOG aggregation: one block per output cell ----------------
__global__ void __launch_bounds__(320) k_agg() {
    __shared__ float acc[11 * 297];
    __shared__ float sfilt[1089];
    int tx = threadIdx.x;            // 0..32  (dx offset)
    int ty = threadIdx.y;            // 0..8
    int t  = ty * 33 + tx;           // 0..296
    int cx = blockIdx.x, cy = blockIdx.y, b = blockIdx.z;

    for (int i = t; i < 11*297; i += 297) acc[i] = 0.0f;
    for (int i = t; i < 1089;   i += 297) sfilt[i] = g_filt[i];

    int c = cx * 16 + tx - 16;
    if (c < 0)   c = -c;
    if (c > 511) c = 1022 - c;
    int r0 = cy * 16 + ty - 16;
    __syncthreads();

    float* accp = acc + t;
    const float* sfp = sfilt + t;

    if (cy >= 1 && cy <= 30) {       // no row reflection needed
        const float4* pp = g_pix + ((size_t)(b << 9) + r0) * 512 + c;
        #pragma unroll
        for (int it = 0; it < 4; it++) {
            int dy = ty + 9 * it;
            if (dy < 33) {
                float4 p = pp[it * 9 * 512];
                float fv = sfp[it * 297];
                int s = __float_as_int(p.z);
                accp[s]       += fv * p.x;
                accp[s + 297] += fv * p.y;
            }
        }
    } else {
        #pragma unroll
        for (int it = 0; it < 4; it++) {
            int dy = ty + 9 * it;
            if (dy < 33) {
                int r = cy * 16 + dy - 16;
                if (r < 0)   r = -r;
                if (r > 511) r = 1022 - r;
                float4 p = g_pix[((size_t)(b << 9) + r) * 512 + c];
                float fv = sfp[it * 297];
                int s = __float_as_int(p.z);
                accp[s]       += fv * p.x;
                accp[s + 297] += fv * p.y;
            }
        }
    }
    __syncthreads();

    int w = t >> 5, lane = t & 31;
    if (w < 9) {                     // warp w reduces bin w (slot w+1)
        const float* row = acc + (w + 1) * 297;
        float s = 0.0f;
        for (int j = lane; j < 297; j += 32) s += row[j];
        #pragma unroll
        for (int o = 16; o > 0; o >>= 1) s += __shfl_xor_sync(0xffffffffu, s, o);
        if (lane == 0)
            g_hog[((size_t)(b * 1024) + cy * 32 + cx) * 9 + w] = s;
    }
}

// ---------------- per-batch norm + eigen + quantize ----------------
__global__ void __launch_bounds__(1024) k_dom() {
    int b = blockIdx.x, t = threadIdx.x;    // t = cell index 0..1023
    const float* h = g_hog + ((size_t)b * 1024 + t) * 9;
    float v[9]; float sq = 0.0f;
    #pragma unroll
    for (int k = 0; k < 9; k++) { v[k] = h[k]; sq += v[k]*v[k]; }

    __shared__ float red[32];
    float m = sq;
    #pragma unroll
    for (int o = 16; o > 0; o >>= 1) m = fmaxf(m, __shfl_xor_sync(0xffffffffu, m, o));
    if ((t & 31) == 0) red[t >> 5] = m;
    __syncthreads();
    if (t < 32) {
        float mm = red[t];
        #pragma unroll
        for (int o = 16; o > 0; o >>= 1) mm = fmaxf(mm, __shfl_xor_sync(0xffffffffu, mm, o));
        if (t == 0) red[0] = mm;
    }
    __syncthreads();
    float maxn = sqrtf(red[0]);

    const float PI_F = 3.1415927410125732f;
    float A = 0.0f, C = 0.0f, Bb = 0.0f;
    #pragma unroll
    for (int k = 0; k < 9; k++) {
        float hn = v[k] / maxn;
        float h2 = hn * hn;
        float cen = 10.0f + 20.0f * (float)k;
        float th  = (cen / 180.0f) * PI_F;
        float s = sinf(th), cc = cosf(th);
        A  += (s * s)  * h2;
        C  += (cc * cc) * h2;
        Bb -= (s * cc) * h2;
    }
    float dd  = (A - C) * 0.5f;
    float lam = (A + C) * 0.5f + sqrtf(dd*dd + Bb*Bb);
    float la = lam - A, lc = lam - C;
    float n1 = Bb*Bb + la*la;
    float n2 = lc*lc + Bb*Bb;
    bool use1 = (n1 >= n2);
    float vx = use1 ? Bb : lc;
    float vy = use1 ? la : Bb;
    float nr = sqrtf(vx*vx + vy*vy) + 1e-9f;
    float dx = vx / nr, dyv = vy / nr;
    g_qv[((size_t)b*2 + 0) * 1024 + t] = floorf((dx  + 1.0f) / 2.0f * 255.0f);
    g_qv[((size_t)b*2 + 1) * 1024 + t] = floorf((dyv + 1.0f) / 2.0f * 255.0f);
}

// ---------------- Lanczos resize along H (32 -> 512) ----------------
__global__ void k_resH() {
    int i = blockIdx.x * blockDim.x + threadIdx.x;  // 8*2*512*32 = 262144
    int x  = i & 31;
    int yo = (i >> 5) & 511;
    int bc = i >> 14;
    float4 wa = g_rwp[yo*2], wb = g_rwp[yo*2+1];
    int j0 = __float_as_int(wb.z);
    float w[6] = {wa.x, wa.y, wa.z, wa.w, wb.x, wb.y};
    const float* q = g_qv + (size_t)bc * 1024 + x;
    float s = 0.0f;
    #pragma unroll
    for (int k = 0; k < 6; k++) {
        int j = j0 + k; j = j < 0 ? 0 : (j > 31 ? 31 : j);
        s += w[k] * q[j * 32];
    }
    g_tmp[((size_t)bc * 512 + yo) * 32 + x] = s;
}

// ---------------- Lanczos resize along W + round/clip/renormalize ----------------
__global__ void __launch_bounds__(512) k_resW(float* __restrict__ out) {
    int b = blockIdx.x >> 9;
    int y = blockIdx.x & 511;
    int tid = threadIdx.x;   // 0..511 = output x
    __shared__ float s0[32], s1[32];
    if (tid < 32)       s0[tid]      = g_tmp[(((size_t)b*2 + 0) * 512 + y) * 32 + tid];
    else if (tid < 64)  s1[tid - 32] = g_tmp[(((size_t)b*2 + 1) * 512 + y) * 32 + (tid - 32)];
    __syncthreads();

    int xo = tid;
    float4 wa = g_rwp[xo*2], wb = g_rwp[xo*2+1];
    int j0 = __float_as_int(wb.z);
    float w[6] = {wa.x, wa.y, wa.z, wa.w, wb.x, wb.y};
    float v0 = 0.0f, v1 = 0.0f;
    #pragma unroll
    for (int k = 0; k < 6; k++) {
        int j = j0 + k; j = j < 0 ? 0 : (j > 31 ? 31 : j);
        v0 += w[k] * s0[j];
        v1 += w[k] * s1[j];
    }
    float r0 = fminf(fmaxf(rintf(v0), 0.0f), 255.0f);
    float r1 = fminf(fmaxf(rintf(v1), 0.0f), 255.0f);
    float o0 = (r0 / 255.0f - 0.5f) * 2.0f;
    float o1 = (r1 / 255.0f - 0.5f) * 2.0f;
    float nr = sqrtf(o0*o0 + o1*o1);
    out[(((size_t)b*2 + 0) * 512 + y) * 512 + xo] = o0 / nr;
    out[(((size_t)b*2 + 1) * 512 + y) * 512 + xo] = o1 / nr;
}

extern "C" void kernel_launch(void* const* d_in, const int* in_sizes, int n_in,
                              void* d_out, int out_size) {
    (void)in_sizes; (void)n_in; (void)out_size;
    const float* x = (const float*)d_in[0];
    float* out = (float*)d_out;

    k_init<<<5, 256>>>();
    k_gray<<<(BATCH*NPIX)/256, 256>>>(x);
    k_grad<<<(BATCH*NPIX)/256, 256>>>();
    k_agg<<<dim3(32, 32, BATCH), dim3(33, 9)>>>();
    k_dom<<<BATCH, 1024>>>();
    k_resH<<<(BATCH*2*512*32)/256, 256>>>();
    k_resW<<<BATCH*512, 512>>>(out);
}

// round 5
// speedup vs baseline: 1.2365x; 1.2365x over previous
#include <cuda_runtime.h>
#include <cstdint>

#define HW    512
#define NPIX  (HW*HW)        // 262144 = 2^18
#define BATCH 8
#define NBINS 9
#define CELLS 32

static __device__ float2 g_pix [BATCH*NPIX];          // 16 MB: (w0 with slot in low 4 bits, w1)
static __device__ float  g_hog [BATCH*CELLS*CELLS*NBINS];
static __device__ float  g_qv  [BATCH*2*CELLS*CELLS]; // quantized dominant dir (as float)
static __device__ float4 g_rwp [HW*2];                // packed lanczos weights: w0..w5, j0(bits), 0
static __device__ float  g_trig[27];                  // ss[9], cc[9], sc[9]

__device__ __forceinline__ float lanczos3(float x) {
    if (x > 3.0f) return 0.0f;
    if (x > 1e-3f) {
        float px = 3.1415927410125732f * x;
        float y  = (3.0f * sinf(px)) * sinf(px / 3.0f);
        return y / (9.8696044921875f * (x * x));
    }
    return 1.0f;
}

// ---------------- init: lanczos resize weights + trig table ----------------
__global__ void k_init() {
    int t = threadIdx.x;
    if (t < HW) {
        float sample = (t + 0.5f) * 0.0625f - 0.5f;
        int j0 = (int)floorf(sample - 3.0f) + 1;
        float w[6]; float wsum = 0.0f;
        #pragma unroll
        for (int k = 0; k < 6; k++) {
            int j = j0 + k;
            float wt = 0.0f;
            if (j >= 0 && j < 32) wt = lanczos3(fabsf(sample - (float)j));
            w[k] = wt; wsum += wt;
        }
        float4 a, b;
        a.x = w[0]/wsum; a.y = w[1]/wsum; a.z = w[2]/wsum; a.w = w[3]/wsum;
        b.x = w[4]/wsum; b.y = w[5]/wsum; b.z = __int_as_float(j0); b.w = 0.0f;
        g_rwp[t*2]   = a;
        g_rwp[t*2+1] = b;
    }
    if (t < 9) {
        const float PI_F = 3.1415927410125732f;
        float cen = 10.0f + 20.0f * (float)t;
        float th  = (cen / 180.0f) * PI_F;
        float s = sinf(th), c = cosf(th);
        g_trig[t]      = s * s;
        g_trig[9 + t]  = c * c;
        g_trig[18 + t] = s * c;
    }
}

// ---------------- fused grayscale + gradient + 2-bin pack ----------------
__global__ void __launch_bounds__(512) k_pre(const float* __restrict__ x) {
    __shared__ float gs[18][34];
    int tx = threadIdx.x, ty = threadIdx.y;       // (32,16)
    int tid = ty * 32 + tx;
    int bx = blockIdx.x * 32, by = blockIdx.y * 16, b = blockIdx.z;
    const float* xb = x + (size_t)b * 3 * NPIX;

    #pragma unroll
    for (int i = tid; i < 18 * 34; i += 512) {
        int r = i / 34, c = i % 34;
        int gr = by + r - 1, gc = bx + c - 1;
        float v = 0.0f;
        if (gr >= 0 && gr < 512 && gc >= 0 && gc < 512) {
            int p = gr * 512 + gc;
            v = xb[p]*0.299f + xb[NPIX+p]*0.587f + xb[2*NPIX+p]*0.114f;
        }
        gs[r][c] = v;
    }
    __syncthreads();

    float gx = gs[ty+1][tx+2] - gs[ty+1][tx];
    float gy = gs[ty+2][tx+1] - gs[ty][tx+1];
    float mag = sqrtf(gx*gx + gy*gy);
    const float PI_F = 3.1415927410125732f;
    float t  = atan2f(gy, gx) + PI_F;
    float o  = fmodf(t, PI_F);
    float orient = (o / PI_F) * 180.0f;
    float f  = orient * 0.05f - 0.5f;
    float fb = floorf(f);
    int   b0 = (int)fb;                           // -1..8
    float frac = f - fb;
    float w0 = mag * (1.0f - frac);
    float w1 = mag * frac;
    unsigned u = (__float_as_uint(w0) & ~15u) | (unsigned)(b0 + 1);  // slot 0..9 in low bits
    float2 v;
    v.x = __uint_as_float(u);
    v.y = w1;
    g_pix[(size_t)b * NPIX + (by + ty) * 512 + (bx + tx)] = v;
}

// ---------------- HOG aggregation: one block per output cell ----------------
// acc[s][t] is float2: .x accumulates w0-contrib (bin s-1), .y accumulates w1-contrib (bin s).
// Row stride 304 float2 => bank = (2t) mod 32, conflict-free for any slot.
#define ACCW 304
__global__ void __launch_bounds__(297) k_agg() {
    __shared__ float2 acc[10 * ACCW];
    int tx = threadIdx.x;            // 0..32  (dx offset)
    int ty = threadIdx.y;            // 0..8
    int t  = ty * 33 + tx;           // 0..296
    int cx = blockIdx.x, cy = blockIdx.y, b = blockIdx.z;

    #pragma unroll
    for (int i = t; i < 10 * ACCW; i += 297) acc[i] = make_float2(0.0f, 0.0f);

    // filter values in registers: filt(dy,dx) = 1 - sqrt(dy^2+dx^2)/(16*sqrt(2))
    float fv[4];
    {
        int dx = tx - 16;
        #pragma unroll
        for (int it = 0; it < 4; it++) {
            int dy = ty + 9 * it - 16;
            float dist = sqrtf((float)(dy*dy + dx*dx));
            fv[it] = 1.0f - dist / 22.627416997969522f;
        }
    }

    int c = cx * 16 + tx - 16;
    if (c < 0)   c = -c;
    if (c > 511) c = 1022 - c;
    int r0 = cy * 16 - 16;
    __syncthreads();

    float2* accb = acc + t;

    if (cy >= 1 && cy <= 30) {       // no row reflection needed
        const float2* pp = g_pix + ((size_t)(b << 9) + r0 + ty) * 512 + c;
        #pragma unroll
        for (int it = 0; it < 4; it++) {
            int dy = ty + 9 * it;
            if (dy < 33) {
                float2 p = pp[it * 9 * 512];
                int slot = __float_as_int(p.x) & 15;
                float2* ap = accb + slot * ACCW;
                float2 a = *ap;
                a.x = fmaf(fv[it], p.x, a.x);
                a.y = fmaf(fv[it], p.y, a.y);
                *ap = a;
            }
        }
    } else {
        #pragma unroll
        for (int it = 0; it < 4; it++) {
            int dy = ty + 9 * it;
            if (dy < 33) {
                int r = r0 + dy;
                if (r < 0)   r = -r;
                if (r > 511) r = 1022 - r;
                float2 p = g_pix[((size_t)(b << 9) + r) * 512 + c];
                int slot = __float_as_int(p.x) & 15;
                float2* ap = accb + slot * ACCW;
                float2 a = *ap;
                a.x = fmaf(fv[it], p.x, a.x);
                a.y = fmaf(fv[it], p.y, a.y);
                *ap = a;
            }
        }
    }
    __syncthreads();

    // bin k = sum_t acc[k+1][t].x + acc[k][t].y ; warp w handles bin w
    int w = t >> 5, lane = t & 31;
    if (t < 288) {
        const float2* rx = acc + (w + 1) * ACCW;
        const float2* ry = acc + w * ACCW;
        float s = 0.0f;
        for (int j = lane; j < 297; j += 32) {
            s += rx[j].x + ry[j].y;
        }
        #pragma unroll
        for (int o = 16; o > 0; o >>= 1) s += __shfl_xor_sync(0xffffffffu, s, o);
        if (lane == 0)
            g_hog[((size_t)(b * 1024) + cy * 32 + cx) * 9 + w] = s;
    }
}

// ---------------- per-batch norm + eigen + quantize ----------------
__global__ void __launch_bounds__(1024) k_dom() {
    int b = blockIdx.x, t = threadIdx.x;    // t = cell index 0..1023
    const float* h = g_hog + ((size_t)b * 1024 + t) * 9;
    float v[9]; float sq = 0.0f;
    #pragma unroll
    for (int k = 0; k < 9; k++) { v[k] = h[k]; sq += v[k]*v[k]; }

    __shared__ float red[32];
    float m = sq;
    #pragma unroll
    for (int o = 16; o > 0; o >>= 1) m = fmaxf(m, __shfl_xor_sync(0xffffffffu, m, o));
    if ((t & 31) == 0) red[t >> 5] = m;
    __syncthreads();
    if (t < 32) {
        float mm = red[t];
        #pragma unroll
        for (int o = 16; o > 0; o >>= 1) mm = fmaxf(mm, __shfl_xor_sync(0xffffffffu, mm, o));
        if (t == 0) red[0] = mm;
    }
    __syncthreads();
    float inv = 1.0f / red[0];              // 1/maxn^2

    float A = 0.0f, C = 0.0f, Bb = 0.0f;
    #pragma unroll
    for (int k = 0; k < 9; k++) {
        float h2 = v[k] * v[k] * inv;
        A  += g_trig[k]      * h2;
        C  += g_trig[9 + k]  * h2;
        Bb -= g_trig[18 + k] * h2;
    }
    float dd  = (A - C) * 0.5f;
    float lam = (A + C) * 0.5f + sqrtf(dd*dd + Bb*Bb);
    float la = lam - A, lc = lam - C;
    float n1 = Bb*Bb + la*la;
    float n2 = lc*lc + Bb*Bb;
    bool use1 = (n1 >= n2);
    float vx = use1 ? Bb : lc;
    float vy = use1 ? la : Bb;
    float nr = sqrtf(vx*vx + vy*vy) + 1e-9f;
    float dx = vx / nr, dyv = vy / nr;
    g_qv[((size_t)b*2 + 0) * 1024 + t] = floorf((dx  + 1.0f) / 2.0f * 255.0f);
    g_qv[((size_t)b*2 + 1) * 1024 + t] = floorf((dyv + 1.0f) / 2.0f * 255.0f);
}

// ---------------- fused Lanczos resize (32x32 -> 512x512) + round/clip/renorm ----------------
__global__ void __launch_bounds__(512) k_res(float* __restrict__ out) {
    int b = blockIdx.x >> 9;
    int y = blockIdx.x & 511;
    int tid = threadIdx.x;   // 0..511 = output x
    __shared__ float tmp[2][32];

    if (tid < 64) {          // H pass for this output row: 2 channels x 32 columns
        int ch = tid >> 5, xx = tid & 31;
        float4 wa = g_rwp[y*2], wb = g_rwp[y*2+1];
        int j0 = __float_as_int(wb.z);
        float w[6] = {wa.x, wa.y, wa.z, wa.w, wb.x, wb.y};
        const float* q = g_qv + ((size_t)b * 2 + ch) * 1024 + xx;
        float s = 0.0f;
        #pragma unroll
        for (int k = 0; k < 6; k++) {
            int j = j0 + k; j = j < 0 ? 0 : (j > 31 ? 31 : j);
            s += w[k] * q[j * 32];
        }
        tmp[ch][xx] = s;
    }
    __syncthreads();

    float4 wa = g_rwp[tid*2], wb = g_rwp[tid*2+1];
    int j0 = __float_as_int(wb.z);
    float w[6] = {wa.x, wa.y, wa.z, wa.w, wb.x, wb.y};
    float v0 = 0.0f, v1 = 0.0f;
    #pragma unroll
    for (int k = 0; k < 6; k++) {
        int j = j0 + k; j = j < 0 ? 0 : (j > 31 ? 31 : j);
        v0 += w[k] * tmp[0][j];
        v1 += w[k] * tmp[1][j];
    }
    float r0 = fminf(fmaxf(rintf(v0), 0.0f), 255.0f);
    float r1 = fminf(fmaxf(rintf(v1), 0.0f), 255.0f);
    float o0 = (r0 / 255.0f - 0.5f) * 2.0f;
    float o1 = (r1 / 255.0f - 0.5f) * 2.0f;
    float nr = sqrtf(o0*o0 + o1*o1);
    out[(((size_t)b*2 + 0) * 512 + y) * 512 + tid] = o0 / nr;
    out[(((size_t)b*2 + 1) * 512 + y) * 512 + tid] = o1 / nr;
}

extern "C" void kernel_launch(void* const* d_in, const int* in_sizes, int n_in,
                              void* d_out, int out_size) {
    (void)in_sizes; (void)n_in; (void)out_size;
    const float* x = (const float*)d_in[0];
    float* out = (float*)d_out;

    k_init<<<1, 512>>>();
    k_pre<<<dim3(16, 32, BATCH), dim3(32, 16)>>>(x);
    k_agg<<<dim3(32, 32, BATCH), dim3(33, 9)>>>();
    k_dom<<<BATCH, 1024>>>();
    k_res<<<BATCH * 512, 512>>>(out);
}

// round 8
// speedup vs baseline: 1.3247x; 1.0714x over previous
#include <cuda_runtime.h>
#include <cstdint>

#define HW    512
#define NPIX  (HW*HW)        // 262144 = 2^18
#define BATCH 8
#define NBINS 9
#define CELLS 32

static __device__ float2 g_pix [BATCH*NPIX];          // 16 MB: (w0 with slot in low 4 bits, w1)
static __device__ float  g_hog [BATCH*NBINS*CELLS*CELLS]; // bin-major: [b][k][cell]
static __device__ int    g_maxsq[BATCH];              // per-batch max cell sqnorm (float bits)
static __device__ float  g_qv  [BATCH*2*CELLS*CELLS]; // quantized dominant dir (as float)
static __device__ float4 g_rwp [HW*2];                // packed lanczos weights: w0..w5, j0(bits), 0
static __device__ float  g_trig[27];                  // ss[9], cc[9], sc[9]

__device__ __forceinline__ float lanczos3(float x) {
    if (x > 3.0f) return 0.0f;
    if (x > 1e-3f) {
        float px = 3.1415927410125732f * x;
        float y  = (3.0f * sinf(px)) * sinf(px / 3.0f);
        return y / (9.8696044921875f * (x * x));
    }
    return 1.0f;
}

// ---------------- fused grayscale + gradient + 2-bin pack (+ table init in block 0) ----------------
__global__ void __launch_bounds__(512) k_pre(const float* __restrict__ x) {
    __shared__ float gs[18][34];
    int tx = threadIdx.x, ty = threadIdx.y;       // (32,16)
    int tid = ty * 32 + tx;
    int bx = blockIdx.x * 32, by = blockIdx.y * 16, b = blockIdx.z;
    const float* xb = x + (size_t)b * 3 * NPIX;

    #pragma unroll
    for (int i = tid; i < 18 * 34; i += 512) {
        int r = i / 34, c = i % 34;
        int gr = by + r - 1, gc = bx + c - 1;
        float v = 0.0f;
        if (gr >= 0 && gr < 512 && gc >= 0 && gc < 512) {
            int p = gr * 512 + gc;
            v = xb[p]*0.299f + xb[NPIX+p]*0.587f + xb[2*NPIX+p]*0.114f;
        }
        gs[r][c] = v;
    }

    // ---- table init, done once by block (0,0,0) (consumers all run in later kernels) ----
    if (blockIdx.x == 0 && blockIdx.y == 0 && blockIdx.z == 0) {
        int t = tid;
        if (t < 8) g_maxsq[t] = 0;
        if (t < HW) {
            float sample = (t + 0.5f) * 0.0625f - 0.5f;
            int j0 = (int)floorf(sample - 3.0f) + 1;
            float w[6]; float wsum = 0.0f;
            #pragma unroll
            for (int k = 0; k < 6; k++) {
                int j = j0 + k;
                float wt = 0.0f;
                if (j >= 0 && j < 32) wt = lanczos3(fabsf(sample - (float)j));
                w[k] = wt; wsum += wt;
            }
            float4 a, bb;
            a.x = w[0]/wsum; a.y = w[1]/wsum; a.z = w[2]/wsum; a.w = w[3]/wsum;
            bb.x = w[4]/wsum; bb.y = w[5]/wsum; bb.z = __int_as_float(j0); bb.w = 0.0f;
            g_rwp[t*2]   = a;
            g_rwp[t*2+1] = bb;
        }
        if (t < 9) {
            const float PI_F = 3.1415927410125732f;
            float cen = 10.0f + 20.0f * (float)t;
            float th  = (cen / 180.0f) * PI_F;
            float s = sinf(th), c = cosf(th);
            g_trig[t]      = s * s;
            g_trig[9 + t]  = c * c;
            g_trig[18 + t] = s * c;
        }
    }
    __syncthreads();

    float gx = gs[ty+1][tx+2] - gs[ty+1][tx];
    float gy = gs[ty+2][tx+1] - gs[ty][tx+1];
    float mag = sqrtf(gx*gx + gy*gy);
    const float PI_F = 3.1415927410125732f;
    float t  = atan2f(gy, gx) + PI_F;
    float o  = fmodf(t, PI_F);
    float orient = (o / PI_F) * 180.0f;
    float f  = orient * 0.05f - 0.5f;
    float fb = floorf(f);
    int   b0 = (int)fb;                           // -1..8
    float frac = f - fb;
    float w0 = mag * (1.0f - frac);
    float w1 = mag * frac;
    unsigned u = (__float_as_uint(w0) & ~15u) | (unsigned)(b0 + 1);  // slot 0..9 in low bits
    float2 v;
    v.x = __uint_as_float(u);
    v.y = w1;
    g_pix[(size_t)b * NPIX + (by + ty) * 512 + (bx + tx)] = v;
}

// ---------------- HOG aggregation: one block per output cell ----------------
// acc[s][t] float2: .x accumulates w0-contrib (bin s-1), .y accumulates w1-contrib (bin s).
// Row stride 304 float2 => bank = (2t) mod 32, conflict-free for any slot.
#define ACCW 304
__global__ void __launch_bounds__(297) k_agg() {
    __shared__ float2 acc[10 * ACCW];
    __shared__ float  bins9[9];
    int tx = threadIdx.x;            // 0..32  (dx offset)
    int ty = threadIdx.y;            // 0..8
    int t  = ty * 33 + tx;           // 0..296
    int cx = blockIdx.x, cy = blockIdx.y, b = blockIdx.z;

    #pragma unroll
    for (int i = t; i < 10 * ACCW; i += 297) acc[i] = make_float2(0.0f, 0.0f);

    // filter values in registers: filt(dy,dx) = 1 - sqrt(dy^2+dx^2)/(16*sqrt(2))
    float fv[4];
    {
        int dx = tx - 16;
        #pragma unroll
        for (int it = 0; it < 4; it++) {
            int dy = ty + 9 * it - 16;
            float dist = sqrtf((float)(dy*dy + dx*dx));
            fv[it] = 1.0f - dist / 22.627416997969522f;
        }
    }

    int c = cx * 16 + tx - 16;
    if (c < 0)   c = -c;
    if (c > 511) c = 1022 - c;
    int r0 = cy * 16 - 16;
    __syncthreads();

    float2* accb = acc + t;
    bool tail = (ty + 27 < 33);      // it=3 valid only for ty<6

    if (cy >= 1 && cy <= 30) {       // no row reflection needed
        const float2* pp = g_pix + ((size_t)(b << 9) + r0 + ty) * 512 + c;
        #pragma unroll
        for (int it = 0; it < 3; it++) {
            float2 p = pp[it * 9 * 512];
            int slot = __float_as_int(p.x) & 15;
            float2* ap = accb + slot * ACCW;
            float2 a = *ap;
            a.x = fmaf(fv[it], p.x, a.x);
            a.y = fmaf(fv[it], p.y, a.y);
            *ap = a;
        }
        if (tail) {
            float2 p = pp[3 * 9 * 512];
            int slot = __float_as_int(p.x) & 15;
            float2* ap = accb + slot * ACCW;
            float2 a = *ap;
            a.x = fmaf(fv[3], p.x, a.x);
            a.y = fmaf(fv[3], p.y, a.y);
            *ap = a;
        }
    } else {
        #pragma unroll
        for (int it = 0; it < 4; it++) {
            int dy = ty + 9 * it;
            if (dy < 33) {
                int r = r0 + dy;
                if (r < 0)   r = -r;
                if (r > 511) r = 1022 - r;
                float2 p = g_pix[((size_t)(b << 9) + r) * 512 + c];
                int slot = __float_as_int(p.x) & 15;
                float2* ap = accb + slot * ACCW;
                float2 a = *ap;
                a.x = fmaf(fv[it], p.x, a.x);
                a.y = fmaf(fv[it], p.y, a.y);
                *ap = a;
            }
        }
    }
    __syncthreads();

    // bin k = sum_t acc[k+1][t].x + acc[k][t].y ; warp w handles bin w
    int w = t >> 5, lane = t & 31;
    if (t < 288) {
        const float2* rx = acc + (w + 1) * ACCW;
        const float2* ry = acc + w * ACCW;
        float s = 0.0f;
        for (int j = lane; j < 297; j += 32) {
            s += rx[j].x + ry[j].y;
        }
        #pragma unroll
        for (int o = 16; o > 0; o >>= 1) s += __shfl_xor_sync(0xffffffffu, s, o);
        if (lane == 0) {
            // bin-major layout for coalesced k_dom loads
            g_hog[(((size_t)b * 9 + w) << 10) + (cy << 5) + cx] = s;
            bins9[w] = s;
        }
    }
    __syncthreads();
    if (t == 0) {
        float sq = 0.0f;
        #pragma unroll
        for (int k = 0; k < 9; k++) sq += bins9[k] * bins9[k];
        atomicMax(&g_maxsq[b], __float_as_int(sq));   // sq >= 0: int-bit order == float order
    }
}

// ---------------- per-cell eigen + quantize (flat grid, per-batch max precomputed) ----------------
__global__ void __launch_bounds__(128) k_dom() {
    int i = blockIdx.x * 128 + threadIdx.x;   // 8192
    int b = i >> 10, cell = i & 1023;
    float inv = 1.0f / __int_as_float(g_maxsq[b]);    // 1/maxn^2

    float A = 0.0f, C = 0.0f, Bb = 0.0f;
    #pragma unroll
    for (int k = 0; k < 9; k++) {
        float v = g_hog[(((size_t)b * 9 + k) << 10) + cell];
        float h2 = v * v * inv;
        A  += g_trig[k]      * h2;
        C  += g_trig[9 + k]  * h2;
        Bb -= g_trig[18 + k] * h2;
    }
    float dd  = (A - C) * 0.5f;
    float lam = (A + C) * 0.5f + sqrtf(dd*dd + Bb*Bb);
    float la = lam - A, lc = lam - C;
    float n1 = Bb*Bb + la*la;
    float n2 = lc*lc + Bb*Bb;
    bool use1 = (n1 >= n2);
    float vx = use1 ? Bb : lc;
    float vy = use1 ? la : Bb;
    float nr = sqrtf(vx*vx + vy*vy) + 1e-9f;
    float dx = vx / nr, dyv = vy / nr;
    g_qv[((size_t)b*2 + 0) * 1024 + cell] = floorf((dx  + 1.0f) / 2.0f * 255.0f);
    g_qv[((size_t)b*2 + 1) * 1024 + cell] = floorf((dyv + 1.0f) / 2.0f * 255.0f);
}

// ---------------- fused Lanczos resize (32x32 -> 512x512) + round/clip/renorm ----------------
__global__ void __launch_bounds__(512) k_res(float* __restrict__ out) {
    int b = blockIdx.x >> 9;
    int y = blockIdx.x & 511;
    int tid = threadIdx.x;   // 0..511 = output x
    __shared__ float tmp[2][32];

    if (tid < 64) {          // H pass for this output row: 2 channels x 32 columns
        int ch = tid >> 5, xx = tid & 31;
        float4 wa = g_rwp[y*2], wb = g_rwp[y*2+1];
        int j0 = __float_as_int(wb.z);
        float w[6] = {wa.x, wa.y, wa.z, wa.w, wb.x, wb.y};
        const float* q = g_qv + ((size_t)b * 2 + ch) * 1024 + xx;
        float s = 0.0f;
        #pragma unroll
        for (int k = 0; k < 6; k++) {
            int j = j0 + k; j = j < 0 ? 0 : (j > 31 ? 31 : j);
            s += w[k] * q[j * 32];
        }
        tmp[ch][xx] = s;
    }
    __syncthreads();

    float4 wa = g_rwp[tid*2], wb = g_rwp[tid*2+1];
    int j0 = __float_as_int(wb.z);
    float w[6] = {wa.x, wa.y, wa.z, wa.w, wb.x, wb.y};
    float v0 = 0.0f, v1 = 0.0f;
    #pragma unroll
    for (int k = 0; k < 6; k++) {
        int j = j0 + k; j = j < 0 ? 0 : (j > 31 ? 31 : j);
        v0 += w[k] * tmp[0][j];
        v1 += w[k] * tmp[1][j];
    }
    float r0 = fminf(fmaxf(rintf(v0), 0.0f), 255.0f);
    float r1 = fminf(fmaxf(rintf(v1), 0.0f), 255.0f);
    float o0 = (r0 / 255.0f - 0.5f) * 2.0f;
    float o1 = (r1 / 255.0f - 0.5f) * 2.0f;
    float nr = sqrtf(o0*o0 + o1*o1);
    out[(((size_t)b*2 + 0) * 512 + y) * 512 + tid] = o0 / nr;
    out[(((size_t)b*2 + 1) * 512 + y) * 512 + tid] = o1 / nr;
}

extern "C" void kernel_launch(void* const* d_in, const int* in_sizes, int n_in,
                              void* d_out, int out_size) {
    (void)in_sizes; (void)n_in; (void)out_size;
    const float* x = (const float*)d_in[0];
    float* out = (float*)d_out;

    k_pre<<<dim3(16, 32, BATCH), dim3(32, 16)>>>(x);
    k_agg<<<dim3(32, 32, BATCH), dim3(33, 9)>>>();
    k_dom<<<64, 128>>>();
    k_res<<<BATCH * 512, 512>>>(out);
}

// round 9
// speedup vs baseline: 1.4809x; 1.1179x over previous
#include <cuda_runtime.h>
#include <cstdint>

#define HW    512
#define NPIX  (HW*HW)        // 262144 = 2^18
#define BATCH 8
#define NBINS 9
#define CELLS 32

static __device__ float2 g_pix [BATCH*NPIX];          // 16 MB: (w0 with slot in low 4 bits, w1)
static __device__ float  g_hog [BATCH*NBINS*CELLS*CELLS]; // bin-major: [b][k][cell]
static __device__ int    g_maxsq[BATCH];              // per-batch max cell sqnorm (float bits)
static __device__ float  g_qv  [BATCH*2*CELLS*CELLS]; // quantized dominant dir (as float)
static __device__ float4 g_rwp [HW*2];                // packed lanczos weights: w0..w5, j0(bits), 0
static __device__ float  g_trig[27];                  // ss[9], cc[9], sc[9]

__device__ __forceinline__ float lanczos3(float x) {
    if (x > 3.0f) return 0.0f;
    if (x > 1e-3f) {
        float px = 3.1415927410125732f * x;
        float y  = (3.0f * sinf(px)) * sinf(px / 3.0f);
        return y / (9.8696044921875f * (x * x));
    }
    return 1.0f;
}

// ---------------- fused grayscale + gradient + 2-bin pack (+ table init in block 0) ----------------
__global__ void __launch_bounds__(512) k_pre(const float* __restrict__ x) {
    __shared__ float gs[18][34];
    int tx = threadIdx.x, ty = threadIdx.y;       // (32,16)
    int tid = ty * 32 + tx;
    int bx = blockIdx.x * 32, by = blockIdx.y * 16, b = blockIdx.z;
    const float* xb = x + (size_t)b * 3 * NPIX;

    #pragma unroll
    for (int i = tid; i < 18 * 34; i += 512) {
        int r = i / 34, c = i % 34;
        int gr = by + r - 1, gc = bx + c - 1;
        float v = 0.0f;
        if (gr >= 0 && gr < 512 && gc >= 0 && gc < 512) {
            int p = gr * 512 + gc;
            v = xb[p]*0.299f + xb[NPIX+p]*0.587f + xb[2*NPIX+p]*0.114f;
        }
        gs[r][c] = v;
    }

    // ---- table init, done once by block (0,0,0) (consumers all run in later kernels) ----
    if (blockIdx.x == 0 && blockIdx.y == 0 && blockIdx.z == 0) {
        int t = tid;
        if (t < 8) g_maxsq[t] = 0;
        if (t < HW) {
            float sample = (t + 0.5f) * 0.0625f - 0.5f;
            int j0 = (int)floorf(sample - 3.0f) + 1;
            float w[6]; float wsum = 0.0f;
            #pragma unroll
            for (int k = 0; k < 6; k++) {
                int j = j0 + k;
                float wt = 0.0f;
                if (j >= 0 && j < 32) wt = lanczos3(fabsf(sample - (float)j));
                w[k] = wt; wsum += wt;
            }
            float4 a, bb;
            a.x = w[0]/wsum; a.y = w[1]/wsum; a.z = w[2]/wsum; a.w = w[3]/wsum;
            bb.x = w[4]/wsum; bb.y = w[5]/wsum; bb.z = __int_as_float(j0); bb.w = 0.0f;
            g_rwp[t*2]   = a;
            g_rwp[t*2+1] = bb;
        }
        if (t < 9) {
            const float PI_F = 3.1415927410125732f;
            float cen = 10.0f + 20.0f * (float)t;
            float th  = (cen / 180.0f) * PI_F;
            float s = sinf(th), c = cosf(th);
            g_trig[t]      = s * s;
            g_trig[9 + t]  = c * c;
            g_trig[18 + t] = s * c;
        }
    }
    __syncthreads();

    float gx = gs[ty+1][tx+2] - gs[ty+1][tx];
    float gy = gs[ty+2][tx+1] - gs[ty][tx+1];
    float mag = sqrtf(gx*gx + gy*gy);
    const float PI_F = 3.1415927410125732f;
    float t  = atan2f(gy, gx) + PI_F;
    float o  = fmodf(t, PI_F);
    float orient = (o / PI_F) * 180.0f;
    float f  = orient * 0.05f - 0.5f;
    float fb = floorf(f);
    int   b0 = (int)fb;                           // -1..8
    float frac = f - fb;
    float w0 = mag * (1.0f - frac);
    float w1 = mag * frac;
    unsigned u = (__float_as_uint(w0) & ~15u) | (unsigned)(b0 + 1);  // slot 0..9 in low bits
    float2 v;
    v.x = __uint_as_float(u);
    v.y = w1;
    g_pix[(size_t)b * NPIX + (by + ty) * 512 + (bx + tx)] = v;
}

// ---------------- HOG aggregation: one block per output cell ----------------
// acc[s][t] float2: .x accumulates w0-contrib (bin s-1), .y accumulates w1-contrib (bin s).
// Row stride 304 float2 => bank = (2t) mod 32, conflict-free for any slot.
#define ACCW 304
__global__ void __launch_bounds__(297) k_agg() {
    __shared__ float2 acc[10 * ACCW];
    __shared__ float  bins9[9];
    int tx = threadIdx.x;            // 0..32  (dx offset)
    int ty = threadIdx.y;            // 0..8
    int t  = ty * 33 + tx;           // 0..296
    int cx = blockIdx.x, cy = blockIdx.y, b = blockIdx.z;

    #pragma unroll
    for (int i = t; i < 10 * ACCW; i += 297) acc[i] = make_float2(0.0f, 0.0f);

    // filter values in registers: filt(dy,dx) = 1 - sqrt(dy^2+dx^2)/(16*sqrt(2))
    float fv[4];
    {
        int dx = tx - 16;
        #pragma unroll
        for (int it = 0; it < 4; it++) {
            int dy = ty + 9 * it - 16;
            float dist = sqrtf((float)(dy*dy + dx*dx));
            fv[it] = 1.0f - dist / 22.627416997969522f;
        }
    }

    int c = cx * 16 + tx - 16;
    if (c < 0)   c = -c;
    if (c > 511) c = 1022 - c;
    int r0 = cy * 16 - 16;
    __syncthreads();

    float2* accb = acc + t;
    bool tail = (ty + 27 < 33);      // it=3 valid only for ty<6

    if (cy >= 1 && cy <= 30) {       // no row reflection needed
        const float2* pp = g_pix + ((size_t)(b << 9) + r0 + ty) * 512 + c;
        #pragma unroll
        for (int it = 0; it < 3; it++) {
            float2 p = pp[it * 9 * 512];
            int slot = __float_as_int(p.x) & 15;
            float2* ap = accb + slot * ACCW;
            float2 a = *ap;
            a.x = fmaf(fv[it], p.x, a.x);
            a.y = fmaf(fv[it], p.y, a.y);
            *ap = a;
        }
        if (tail) {
            float2 p = pp[3 * 9 * 512];
            int slot = __float_as_int(p.x) & 15;
            float2* ap = accb + slot * ACCW;
            float2 a = *ap;
            a.x = fmaf(fv[3], p.x, a.x);
            a.y = fmaf(fv[3], p.y, a.y);
            *ap = a;
        }
    } else {
        #pragma unroll
        for (int it = 0; it < 4; it++) {
            int dy = ty + 9 * it;
            if (dy < 33) {
                int r = r0 + dy;
                if (r < 0)   r = -r;
                if (r > 511) r = 1022 - r;
                float2 p = g_pix[((size_t)(b << 9) + r) * 512 + c];
                int slot = __float_as_int(p.x) & 15;
                float2* ap = accb + slot * ACCW;
                float2 a = *ap;
                a.x = fmaf(fv[it], p.x, a.x);
                a.y = fmaf(fv[it], p.y, a.y);
                *ap = a;
            }
        }
    }
    __syncthreads();

    // bin k = sum_t acc[k+1][t].x + acc[k][t].y ; warp w handles bin w
    int w = t >> 5, lane = t & 31;
    if (t < 288) {
        const float2* rx = acc + (w + 1) * ACCW;
        const float2* ry = acc + w * ACCW;
        float s = 0.0f;
        for (int j = lane; j < 297; j += 32) {
            s += rx[j].x + ry[j].y;
        }
        #pragma unroll
        for (int o = 16; o > 0; o >>= 1) s += __shfl_xor_sync(0xffffffffu, s, o);
        if (lane == 0) {
            // bin-major layout for coalesced k_dom loads
            g_hog[(((size_t)b * 9 + w) << 10) + (cy << 5) + cx] = s;
            bins9[w] = s;
        }
    }
    __syncthreads();
    if (t == 0) {
        float sq = 0.0f;
        #pragma unroll
        for (int k = 0; k < 9; k++) sq += bins9[k] * bins9[k];
        atomicMax(&g_maxsq[b], __float_as_int(sq));   // sq >= 0: int-bit order == float order
    }
}

// ---------------- per-cell eigen + quantize (flat grid, per-batch max precomputed) ----------------
__global__ void __launch_bounds__(128) k_dom() {
    int i = blockIdx.x * 128 + threadIdx.x;   // 8192
    int b = i >> 10, cell = i & 1023;
    float inv = 1.0f / __int_as_float(g_maxsq[b]);    // 1/maxn^2

    float A = 0.0f, C = 0.0f, Bb = 0.0f;
    #pragma unroll
    for (int k = 0; k < 9; k++) {
        float v = g_hog[(((size_t)b * 9 + k) << 10) + cell];
        float h2 = v * v * inv;
        A  += g_trig[k]      * h2;
        C  += g_trig[9 + k]  * h2;
        Bb -= g_trig[18 + k] * h2;
    }
    float dd  = (A - C) * 0.5f;
    float lam = (A + C) * 0.5f + sqrtf(dd*dd + Bb*Bb);
    float la = lam - A, lc = lam - C;
    float n1 = Bb*Bb + la*la;
    float n2 = lc*lc + Bb*Bb;
    bool use1 = (n1 >= n2);
    float vx = use1 ? Bb : lc;
    float vy = use1 ? la : Bb;
    float nr = sqrtf(vx*vx + vy*vy) + 1e-9f;
    float dx = vx / nr, dyv = vy / nr;
    g_qv[((size_t)b*2 + 0) * 1024 + cell] = floorf((dx  + 1.0f) / 2.0f * 255.0f);
    g_qv[((size_t)b*2 + 1) * 1024 + cell] = floorf((dyv + 1.0f) / 2.0f * 255.0f);
}

// ---------------- fused Lanczos resize (32x32 -> 512x512), 4 rows per block ----------------
// H-pass result kept as float2 (ch0,ch1) so W-pass does 6 LDS.64/row instead of 12 LDS.32.
// Final renormalize uses scale invariance: out = u/sqrt(u0^2+u1^2) with u = 2*r - 255.
#define RROWS 4
__global__ void __launch_bounds__(512) k_res(float* __restrict__ out) {
    int b  = blockIdx.x >> 7;            // 0..7
    int y0 = (blockIdx.x & 127) * RROWS; // base output row
    int tid = threadIdx.x;               // 0..511
    __shared__ float2 tmp[RROWS][32];    // [row][col] = (ch0, ch1)

    if (tid < RROWS * 64) {              // H pass: RROWS rows x 2 ch x 32 cols
        int row = tid >> 6, ch = (tid >> 5) & 1, xx = tid & 31;
        int y = y0 + row;
        float4 wa = g_rwp[y*2], wb = g_rwp[y*2+1];
        int j0 = __float_as_int(wb.z);
        float w[6] = {wa.x, wa.y, wa.z, wa.w, wb.x, wb.y};
        const float* q = g_qv + ((size_t)b * 2 + ch) * 1024 + xx;
        float s = 0.0f;
        #pragma unroll
        for (int k = 0; k < 6; k++) {
            int j = j0 + k; j = j < 0 ? 0 : (j > 31 ? 31 : j);
            s += w[k] * q[j * 32];
        }
        ((float*)&tmp[row][xx])[ch] = s;
    }
    __syncthreads();

    // W pass: weights + clamped indices depend only on x = tid -> compute once, reuse 4 rows
    float4 wa = g_rwp[tid*2], wb = g_rwp[tid*2+1];
    int j0 = __float_as_int(wb.z);
    float w[6] = {wa.x, wa.y, wa.z, wa.w, wb.x, wb.y};
    int jj[6];
    #pragma unroll
    for (int k = 0; k < 6; k++) {
        int j = j0 + k; jj[k] = j < 0 ? 0 : (j > 31 ? 31 : j);
    }

    float* o0p = out + (((size_t)b*2 + 0) * 512 + y0) * 512 + tid;
    float* o1p = out + (((size_t)b*2 + 1) * 512 + y0) * 512 + tid;
    #pragma unroll
    for (int row = 0; row < RROWS; row++) {
        float v0 = 0.0f, v1 = 0.0f;
        #pragma unroll
        for (int k = 0; k < 6; k++) {
            float2 tv = tmp[row][jj[k]];
            v0 = fmaf(w[k], tv.x, v0);
            v1 = fmaf(w[k], tv.y, v1);
        }
        float r0 = fminf(fmaxf(rintf(v0), 0.0f), 255.0f);
        float r1 = fminf(fmaxf(rintf(v1), 0.0f), 255.0f);
        float u0 = fmaf(2.0f, r0, -255.0f);
        float u1 = fmaf(2.0f, r1, -255.0f);
        float wn = rsqrtf(u0*u0 + u1*u1);
        o0p[row * 512] = u0 * wn;
        o1p[row * 512] = u1 * wn;
    }
}

extern "C" void kernel_launch(void* const* d_in, const int* in_sizes, int n_in,
                              void* d_out, int out_size) {
    (void)in_sizes; (void)n_in; (void)out_size;
    const float* x = (const float*)d_in[0];
    float* out = (float*)d_out;

    k_pre<<<dim3(16, 32, BATCH), dim3(32, 16)>>>(x);
    k_agg<<<dim3(32, 32, BATCH), dim3(33, 9)>>>();
    k_dom<<<64, 128>>>();
    k_res<<<BATCH * 128, 512>>>(out);
}

// round 11
// speedup vs baseline: 1.5834x; 1.0692x over previous
#include <cuda_runtime.h>
#include <cstdint>

#define HW    512
#define NPIX  (HW*HW)        // 262144 = 2^18
#define BATCH 8
#define NBINS 9
#define CELLS 32

static __device__ float2 g_pix [BATCH*NPIX];          // 16 MB: (w0 with slot in low 4 bits, w1)
static __device__ float  g_hog [BATCH*NBINS*CELLS*CELLS]; // bin-major: [b][k][cell]
static __device__ int    g_maxsq[BATCH];              // per-batch max cell sqnorm (float bits)
static __device__ float  g_qv  [BATCH*2*CELLS*CELLS]; // quantized dominant dir (as float)
static __device__ float4 g_rwp [HW*2];                // packed lanczos weights: w0..w5, j0(bits), 0
static __device__ float  g_trig[27];                  // ss[9], cc[9], sc[9]

__device__ __forceinline__ float lanczos3(float x) {
    if (x > 3.0f) return 0.0f;
    if (x > 1e-3f) {
        float px = 3.1415927410125732f * x;
        float y  = (3.0f * sinf(px)) * sinf(px / 3.0f);
        return y / (9.8696044921875f * (x * x));
    }
    return 1.0f;
}

// ---------------- fused grayscale + gradient + 2-bin pack (+ table init in block 0) ----------------
__global__ void __launch_bounds__(512) k_pre(const float* __restrict__ x) {
    __shared__ float gs[18][34];
    int tx = threadIdx.x, ty = threadIdx.y;       // (32,16)
    int tid = ty * 32 + tx;
    int bx = blockIdx.x * 32, by = blockIdx.y * 16, b = blockIdx.z;
    const float* xb = x + (size_t)b * 3 * NPIX;

    #pragma unroll
    for (int i = tid; i < 18 * 34; i += 512) {
        int r = i / 34, c = i % 34;
        int gr = by + r - 1, gc = bx + c - 1;
        float v = 0.0f;
        if (gr >= 0 && gr < 512 && gc >= 0 && gc < 512) {
            int p = gr * 512 + gc;
            v = xb[p]*0.299f + xb[NPIX+p]*0.587f + xb[2*NPIX+p]*0.114f;
        }
        gs[r][c] = v;
    }

    // ---- table init, done once by block (0,0,0) (consumers all run in later kernels) ----
    if (blockIdx.x == 0 && blockIdx.y == 0 && blockIdx.z == 0) {
        int t = tid;
        if (t < 8) g_maxsq[t] = 0;
        if (t < HW) {
            float sample = (t + 0.5f) * 0.0625f - 0.5f;
            int j0 = (int)floorf(sample - 3.0f) + 1;
            float w[6]; float wsum = 0.0f;
            #pragma unroll
            for (int k = 0; k < 6; k++) {
                int j = j0 + k;
                float wt = 0.0f;
                if (j >= 0 && j < 32) wt = lanczos3(fabsf(sample - (float)j));
                w[k] = wt; wsum += wt;
            }
            float4 a, bb;
            a.x = w[0]/wsum; a.y = w[1]/wsum; a.z = w[2]/wsum; a.w = w[3]/wsum;
            bb.x = w[4]/wsum; bb.y = w[5]/wsum; bb.z = __int_as_float(j0); bb.w = 0.0f;
            g_rwp[t*2]   = a;
            g_rwp[t*2+1] = bb;
        }
        if (t < 9) {
            const float PI_F = 3.1415927410125732f;
            float cen = 10.0f + 20.0f * (float)t;
            float th  = (cen / 180.0f) * PI_F;
            float s = sinf(th), c = cosf(th);
            g_trig[t]      = s * s;
            g_trig[9 + t]  = c * c;
            g_trig[18 + t] = s * c;
        }
    }
    __syncthreads();

    float gx = gs[ty+1][tx+2] - gs[ty+1][tx];
    float gy = gs[ty+2][tx+1] - gs[ty][tx+1];
    float mag = sqrtf(gx*gx + gy*gy);
    const float PI_F = 3.1415927410125732f;
    float t  = atan2f(gy, gx) + PI_F;
    float o  = fmodf(t, PI_F);
    float orient = (o / PI_F) * 180.0f;
    float f  = orient * 0.05f - 0.5f;
    float fb = floorf(f);
    int   b0 = (int)fb;                           // -1..8
    float frac = f - fb;
    float w0 = mag * (1.0f - frac);
    float w1 = mag * frac;
    unsigned u = (__float_as_uint(w0) & ~15u) | (unsigned)(b0 + 1);  // slot 0..9 in low bits
    float2 v;
    v.x = __uint_as_float(u);
    v.y = w1;
    g_pix[(size_t)b * NPIX + (by + ty) * 512 + (bx + tx)] = v;
}

// ---------------- HOG aggregation: one block per output cell ----------------
// acc[s][t] float2: .x accumulates w0-contrib (bin s-1), .y accumulates w1-contrib (bin s).
// Row stride 304 float2 => bank = (2t) mod 32, conflict-free for any slot.
// 320 threads: t<297 do the accumulation; all 10 warps do init + per-row reduction.
#define ACCW 304
__global__ void __launch_bounds__(320) k_agg() {
    __shared__ __align__(16) float2 acc[10 * ACCW];
    __shared__ float2 rowsum[10];
    int t = threadIdx.x;             // 0..319
    int cx = blockIdx.x, cy = blockIdx.y, b = blockIdx.z;

    // init via float4 (10*ACCW float2 = 5*ACCW float4 = 1520)
    float4* ai = (float4*)acc;
    for (int i = t; i < 5 * ACCW; i += 320) ai[i] = make_float4(0.f, 0.f, 0.f, 0.f);

    int tx = t % 33, ty = t / 33;    // valid mapping for t<297
    // filter values in registers: filt(dy,dx) = 1 - sqrt(dy^2+dx^2)/(16*sqrt(2))
    float fv[4];
    {
        int dx = tx - 16;
        #pragma unroll
        for (int it = 0; it < 4; it++) {
            int dy = ty + 9 * it - 16;
            float dist = sqrtf((float)(dy*dy + dx*dx));
            fv[it] = 1.0f - dist / 22.627416997969522f;
        }
    }
    int c = cx * 16 + tx - 16;
    if (c < 0)   c = -c;
    if (c > 511) c = 1022 - c;
    int r0 = cy * 16 - 16;
    __syncthreads();

    if (t < 297) {
        float2* accb = acc + t;
        bool tail = (ty < 6);            // it=3 valid only for ty<6 (dy<33)
        if (cy >= 1 && cy <= 30) {       // no row reflection needed
            const float2* pp = g_pix + ((size_t)(b << 9) + r0 + ty) * 512 + c;
            #pragma unroll
            for (int it = 0; it < 3; it++) {
                float2 p = pp[it * 9 * 512];
                int slot = __float_as_int(p.x) & 15;
                float2* ap = accb + slot * ACCW;
                float2 a = *ap;
                a.x = fmaf(fv[it], p.x, a.x);
                a.y = fmaf(fv[it], p.y, a.y);
                *ap = a;
            }
            if (tail) {
                float2 p = pp[3 * 9 * 512];
                int slot = __float_as_int(p.x) & 15;
                float2* ap = accb + slot * ACCW;
                float2 a = *ap;
                a.x = fmaf(fv[3], p.x, a.x);
                a.y = fmaf(fv[3], p.y, a.y);
                *ap = a;
            }
        } else {
            #pragma unroll
            for (int it = 0; it < 4; it++) {
                int dy = ty + 9 * it;
                if (dy < 33) {
                    int r = r0 + dy;
                    if (r < 0)   r = -r;
                    if (r > 511) r = 1022 - r;
                    float2 p = g_pix[((size_t)(b << 9) + r) * 512 + c];
                    int slot = __float_as_int(p.x) & 15;
                    float2* ap = accb + slot * ACCW;
                    float2 a = *ap;
                    a.x = fmaf(fv[it], p.x, a.x);
                    a.y = fmaf(fv[it], p.y, a.y);
                    *ap = a;
                }
            }
        }
    }
    __syncthreads();

    // per-row float2 sums: warp w reduces row w (10 warps, 10 rows)
    {
        int w = t >> 5, lane = t & 31;
        float2 s = make_float2(0.0f, 0.0f);
        const float2* row = acc + w * ACCW;
        for (int j = lane; j < 297; j += 32) {
            float2 v = row[j];
            s.x += v.x; s.y += v.y;
        }
        #pragma unroll
        for (int o = 16; o > 0; o >>= 1) {
            s.x += __shfl_xor_sync(0xffffffffu, s.x, o);
            s.y += __shfl_xor_sync(0xffffffffu, s.y, o);
        }
        if (lane == 0) rowsum[w] = s;
    }
    __syncthreads();

    // bin k = S[k+1].x + S[k].y  (warp 0 only); then 9-lane square-sum + atomicMax
    if (t < 32) {
        float bin = 0.0f;
        if (t < 9) {
            bin = rowsum[t + 1].x + rowsum[t].y;
            g_hog[(((size_t)b * 9 + t) << 10) + (cy << 5) + cx] = bin;
        }
        float sq = bin * bin;
        #pragma unroll
        for (int o = 16; o > 0; o >>= 1) sq += __shfl_xor_sync(0xffffffffu, sq, o);
        if (t == 0) atomicMax(&g_maxsq[b], __float_as_int(sq));  // sq>=0: int order == float order
    }
}

// ---------------- per-cell eigen + quantize (flat grid, per-batch max precomputed) ----------------
__global__ void __launch_bounds__(128) k_dom() {
    int i = blockIdx.x * 128 + threadIdx.x;   // 8192
    int b = i >> 10, cell = i & 1023;
    float inv = 1.0f / __int_as_float(g_maxsq[b]);    // 1/maxn^2

    float A = 0.0f, C = 0.0f, Bb = 0.0f;
    #pragma unroll
    for (int k = 0; k < 9; k++) {
        float v = g_hog[(((size_t)b * 9 + k) << 10) + cell];
        float h2 = v * v * inv;
        A  += g_trig[k]      * h2;
        C  += g_trig[9 + k]  * h2;
        Bb -= g_trig[18 + k] * h2;
    }
    float dd  = (A - C) * 0.5f;
    float lam = (A + C) * 0.5f + sqrtf(dd*dd + Bb*Bb);
    float la = lam - A, lc = lam - C;
    float n1 = Bb*Bb + la*la;
    float n2 = lc*lc + Bb*Bb;
    bool use1 = (n1 >= n2);
    float vx = use1 ? Bb : lc;
    float vy = use1 ? la : Bb;
    float nr = sqrtf(vx*vx + vy*vy) + 1e-9f;
    float dx = vx / nr, dyv = vy / nr;
    g_qv[((size_t)b*2 + 0) * 1024 + cell] = floorf((dx  + 1.0f) / 2.0f * 255.0f);
    g_qv[((size_t)b*2 + 1) * 1024 + cell] = floorf((dyv + 1.0f) / 2.0f * 255.0f);
}

// ---------------- fused Lanczos resize (32x32 -> 512x512), 8 rows per block ----------------
// H-pass keeps both channels as float2 -> 6 LDS.64/row in W pass.
// Renormalize via scale invariance: out = u/sqrt(u0^2+u1^2), u = 2*r - 255 (exact ints).
#define RROWS 8
__global__ void __launch_bounds__(512) k_res(float* __restrict__ out) {
    int b  = blockIdx.x >> 6;            // 0..7
    int y0 = (blockIdx.x & 63) * RROWS;  // base output row
    int tid = threadIdx.x;               // 0..511
    __shared__ float2 tmp[RROWS][32];    // [row][col] = (ch0, ch1)

    {                                    // H pass: 8 rows x 2 ch x 32 cols = 512 threads
        int row = tid >> 6, ch = (tid >> 5) & 1, xx = tid & 31;
        int y = y0 + row;
        float4 wa = g_rwp[y*2], wb = g_rwp[y*2+1];
        int j0 = __float_as_int(wb.z);
        float w[6] = {wa.x, wa.y, wa.z, wa.w, wb.x, wb.y};
        const float* q = g_qv + ((size_t)b * 2 + ch) * 1024 + xx;
        float s = 0.0f;
        #pragma unroll
        for (int k = 0; k < 6; k++) {
            int j = j0 + k; j = j < 0 ? 0 : (j > 31 ? 31 : j);
            s += w[k] * q[j * 32];
        }
        ((float*)&tmp[row][xx])[ch] = s;
    }
    __syncthreads();

    // W pass: weights + clamped indices depend only on x = tid -> compute once, reuse 8 rows
    float4 wa = g_rwp[tid*2], wb = g_rwp[tid*2+1];
    int j0 = __float_as_int(wb.z);
    float w[6] = {wa.x, wa.y, wa.z, wa.w, wb.x, wb.y};
    int jj[6];
    #pragma unroll
    for (int k = 0; k < 6; k++) {
        int j = j0 + k; jj[k] = j < 0 ? 0 : (j > 31 ? 31 : j);
    }

    float* o0p = out + (((size_t)b*2 + 0) * 512 + y0) * 512 + tid;
    float* o1p = out + (((size_t)b*2 + 1) * 512 + y0) * 512 + tid;
    #pragma unroll
    for (int row = 0; row < RROWS; row++) {
        float v0 = 0.0f, v1 = 0.0f;
        #pragma unroll
        for (int k = 0; k < 6; k++) {
            float2 tv = tmp[row][jj[k]];
            v0 = fmaf(w[k], tv.x, v0);
            v1 = fmaf(w[k], tv.y, v1);
        }
        float r0 = fminf(fmaxf(rintf(v0), 0.0f), 255.0f);
        float r1 = fminf(fmaxf(rintf(v1), 0.0f), 255.0f);
        float u0 = fmaf(2.0f, r0, -255.0f);
        float u1 = fmaf(2.0f, r1, -255.0f);
        float wn = rsqrtf(u0*u0 + u1*u1);
        o0p[row * 512] = u0 * wn;
        o1p[row * 512] = u1 * wn;
    }
}

extern "C" void kernel_launch(void* const* d_in, const int* in_sizes, int n_in,
                              void* d_out, int out_size) {
    (void)in_sizes; (void)n_in; (void)out_size;
    const float* x = (const float*)d_in[0];
    float* out = (float*)d_out;

    k_pre<<<dim3(16, 32, BATCH), dim3(32, 16)>>>(x);
    k_agg<<<dim3(32, 32, BATCH), 320>>>();
    k_dom<<<64, 128>>>();
    k_res<<<BATCH * 64, 512>>>(out);
}

// round 12
// speedup vs baseline: 1.8755x; 1.1845x over previous
#include <cuda_runtime.h>
#include <cstdint>
#include <cstdlib>

#define HW    512
#define NPIX  (HW*HW)        // 262144 = 2^18
#define BATCH 8
#define NBINS 9
#define CELLS 32

static __device__ float2 g_pix [BATCH*NPIX];          // 16 MB: (w0 with slot in low 4 bits, w1)
static __device__ float  g_hog [BATCH*NBINS*CELLS*CELLS]; // bin-major: [b][k][cell]
static __device__ int    g_maxsq[BATCH];              // per-batch max cell sqnorm (float bits)
static __device__ float  g_qv  [BATCH*2*CELLS*CELLS]; // quantized dominant dir (as float)
static __device__ float4 g_rwp [HW*2];                // packed lanczos weights: w0..w5, j0(bits), 0
static __device__ float  g_trig[27];                  // ss[9], cc[9], sc[9]

__device__ __forceinline__ float lanczos3(float x) {
    if (x > 3.0f) return 0.0f;
    if (x > 1e-3f) {
        float px = 3.1415927410125732f * x;
        float y  = (3.0f * sinf(px)) * sinf(px / 3.0f);
        return y / (9.8696044921875f * (x * x));
    }
    return 1.0f;
}

// fast atan2 folded into [0, pi]: o = mod(atan2(gy,gx)+pi, pi)
// cephes atanf core (deg-9 poly + tan(pi/8) reduction), ~1e-7 rad abs error.
__device__ __forceinline__ float fold_atan2(float gy, float gx) {
    float gxp = (gy < 0.0f) ? -gx : gx;
    float ay = fabsf(gy);
    float ax = fabsf(gxp);
    float mn = fminf(ax, ay), mx = fmaxf(ax, ay);
    float r = (mx > 0.0f) ? __fdividef(mn, mx) : 0.0f;   // [0,1]
    bool red = r > 0.4142135679721832f;                  // tan(pi/8)
    float t = red ? __fdividef(r - 1.0f, r + 1.0f) : r;  // [-0.414, 0.414]
    float z = t * t;
    float p = fmaf(fmaf(fmaf(8.05374449538e-2f, z, -1.38776856032e-1f), z,
                        1.99777106478e-1f), z, -3.33329491539e-1f);
    p = fmaf(p * z, t, t);
    if (red) p += 0.7853981633974483f;                   // + pi/4
    float a = (ay > ax) ? 1.5707963267948966f - p : p;
    if (gxp < 0.0f) a = 3.14159265358979323846f - a;
    if (ay == 0.0f) a = 0.0f;   // matches fmod(atan2(0,neg)+pi, pi) == 0
    return a;                    // [0, pi]
}

// ---------------- fused grayscale + gradient + 2-bin pack (+ table init in block 0) ----------------
__global__ void __launch_bounds__(512) k_pre(const float* __restrict__ x) {
    __shared__ float gs[18][34];
    int tx = threadIdx.x, ty = threadIdx.y;       // (32,16)
    int tid = ty * 32 + tx;
    int bx = blockIdx.x * 32, by = blockIdx.y * 16, b = blockIdx.z;
    const float* xb = x + (size_t)b * 3 * NPIX;

    #pragma unroll
    for (int i = tid; i < 18 * 34; i += 512) {
        int r = i / 34, c = i % 34;
        int gr = by + r - 1, gc = bx + c - 1;
        float v = 0.0f;
        if (gr >= 0 && gr < 512 && gc >= 0 && gc < 512) {
            int p = gr * 512 + gc;
            v = xb[p]*0.299f + xb[NPIX+p]*0.587f + xb[2*NPIX+p]*0.114f;
        }
        gs[r][c] = v;
    }

    // ---- table init, done once by block (0,0,0) (consumers all run in later kernels) ----
    if (blockIdx.x == 0 && blockIdx.y == 0 && blockIdx.z == 0) {
        int t = tid;
        if (t < 8) g_maxsq[t] = 0;
        if (t < HW) {
            float sample = (t + 0.5f) * 0.0625f - 0.5f;
            int j0 = (int)floorf(sample - 3.0f) + 1;
            float w[6]; float wsum = 0.0f;
            #pragma unroll
            for (int k = 0; k < 6; k++) {
                int j = j0 + k;
                float wt = 0.0f;
                if (j >= 0 && j < 32) wt = lanczos3(fabsf(sample - (float)j));
                w[k] = wt; wsum += wt;
            }
            float4 a, bb;
            a.x = w[0]/wsum; a.y = w[1]/wsum; a.z = w[2]/wsum; a.w = w[3]/wsum;
            bb.x = w[4]/wsum; bb.y = w[5]/wsum; bb.z = __int_as_float(j0); bb.w = 0.0f;
            g_rwp[t*2]   = a;
            g_rwp[t*2+1] = bb;
        }
        if (t < 9) {
            const float PI_F = 3.1415927410125732f;
            float cen = 10.0f + 20.0f * (float)t;
            float th  = (cen / 180.0f) * PI_F;
            float s = sinf(th), c = cosf(th);
            g_trig[t]      = s * s;
            g_trig[9 + t]  = c * c;
            g_trig[18 + t] = s * c;
        }
    }
    __syncthreads();

    float gx = gs[ty+1][tx+2] - gs[ty+1][tx];
    float gy = gs[ty+2][tx+1] - gs[ty][tx+1];
    float mag = sqrtf(gx*gx + gy*gy);
    float o = fold_atan2(gy, gx);                 // [0, pi]
    float orient = o * (180.0f / 3.14159265358979323846f);
    float f  = orient * 0.05f - 0.5f;
    float fb = floorf(f);
    int   b0 = (int)fb;                           // -1..8
    float frac = f - fb;
    float w0 = mag * (1.0f - frac);
    float w1 = mag * frac;
    unsigned u = (__float_as_uint(w0) & ~15u) | (unsigned)(b0 + 1);  // slot 0..9 in low bits
    float2 v;
    v.x = __uint_as_float(u);
    v.y = w1;
    g_pix[(size_t)b * NPIX + (by + ty) * 512 + (bx + tx)] = v;
}

// ---------------- HOG aggregation: one 160-thread block per output cell ----------------
// acc[s][t] float2: .x accumulates w0-contrib (bin s-1), .y accumulates w1-contrib (bin s).
// Row stride 160 float2 => 2*160*slot = 0 mod 32 banks: conflict-free for any slot.
// Each thread walks ~7 pixels of the 33x33 window (flat index t, t+160, ...).
#define AGT  160
#define ACC2 160
__global__ void __launch_bounds__(AGT) k_agg() {
    __shared__ __align__(16) float2 acc[10 * ACC2];
    __shared__ float2 rowsum[10];
    int t = threadIdx.x;             // 0..159
    int cx = blockIdx.x, cy = blockIdx.y, b = blockIdx.z;

    // init via float4: 10*ACC2 float2 = 5*ACC2 float4 = 800
    float4* ai = (float4*)acc;
    #pragma unroll
    for (int i = t; i < 5 * ACC2; i += AGT) ai[i] = make_float4(0.f, 0.f, 0.f, 0.f);

    int r0 = cy * 16 - 16, c0 = cx * 16 - 16;
    const float2* gp = g_pix + ((size_t)b << 18);
    const float invD = 1.0f / 22.627416997969522f;
    __syncthreads();

    float2* accb = acc + t;
    #pragma unroll
    for (int it = 0; it < 7; it++) {
        int i = t + it * AGT;
        if (it < 6 || i < 1089) {            // only last iter needs the guard
            int dy = i / 33;
            int dx = i - dy * 33;
            int r = abs(r0 + dy); if (r > 511) r = 1022 - r;
            int c = abs(c0 + dx); if (c > 511) c = 1022 - c;
            float2 p = gp[(r << 9) + c];
            int qy = dy - 16, qx = dx - 16;
            float dist = sqrtf((float)(qy*qy + qx*qx));
            float fv = fmaf(dist, -invD, 1.0f);
            int slot = __float_as_int(p.x) & 15;
            float2* ap = accb + slot * ACC2;
            float2 a = *ap;
            a.x = fmaf(fv, p.x, a.x);
            a.y = fmaf(fv, p.y, a.y);
            *ap = a;
        }
    }
    __syncthreads();

    // per-row float2 sums: warp w reduces rows w and w+5 (5 warps, 10 rows)
    {
        int w = t >> 5, lane = t & 31;
        #pragma unroll
        for (int rr = 0; rr < 2; rr++) {
            int row = w + rr * 5;
            const float2* rp = acc + row * ACC2;
            float2 s = make_float2(0.0f, 0.0f);
            #pragma unroll
            for (int j = 0; j < 5; j++) {
                float2 v = rp[lane + 32 * j];
                s.x += v.x; s.y += v.y;
            }
            #pragma unroll
            for (int o = 16; o > 0; o >>= 1) {
                s.x += __shfl_xor_sync(0xffffffffu, s.x, o);
                s.y += __shfl_xor_sync(0xffffffffu, s.y, o);
            }
            if (lane == 0) rowsum[row] = s;
        }
    }
    __syncthreads();

    // bin k = S[k+1].x + S[k].y  (warp 0 only); then 9-lane square-sum + atomicMax
    if (t < 32) {
        float bin = 0.0f;
        if (t < 9) {
            bin = rowsum[t + 1].x + rowsum[t].y;
            g_hog[(((size_t)b * 9 + t) << 10) + (cy << 5) + cx] = bin;
        }
        float sq = bin * bin;
        #pragma unroll
        for (int o = 16; o > 0; o >>= 1) sq += __shfl_xor_sync(0xffffffffu, sq, o);
        if (t == 0) atomicMax(&g_maxsq[b], __float_as_int(sq));  // sq>=0: int order == float order
    }
}

// ---------------- per-cell eigen + quantize (flat grid, per-batch max precomputed) ----------------
__global__ void __launch_bounds__(128) k_dom() {
    int i = blockIdx.x * 128 + threadIdx.x;   // 8192
    int b = i >> 10, cell = i & 1023;
    float inv = 1.0f / __int_as_float(g_maxsq[b]);    // 1/maxn^2

    float A = 0.0f, C = 0.0f, Bb = 0.0f;
    #pragma unroll
    for (int k = 0; k < 9; k++) {
        float v = g_hog[(((size_t)b * 9 + k) << 10) + cell];
        float h2 = v * v * inv;
        A  += g_trig[k]      * h2;
        C  += g_trig[9 + k]  * h2;
        Bb -= g_trig[18 + k] * h2;
    }
    float dd  = (A - C) * 0.5f;
    float lam = (A + C) * 0.5f + sqrtf(dd*dd + Bb*Bb);
    float la = lam - A, lc = lam - C;
    float n1 = Bb*Bb + la*la;
    float n2 = lc*lc + Bb*Bb;
    bool use1 = (n1 >= n2);
    float vx = use1 ? Bb : lc;
    float vy = use1 ? la : Bb;
    float nr = sqrtf(vx*vx + vy*vy) + 1e-9f;
    float dx = vx / nr, dyv = vy / nr;
    g_qv[((size_t)b*2 + 0) * 1024 + cell] = floorf((dx  + 1.0f) / 2.0f * 255.0f);
    g_qv[((size_t)b*2 + 1) * 1024 + cell] = floorf((dyv + 1.0f) / 2.0f * 255.0f);
}

// ---------------- fused Lanczos resize (32x32 -> 512x512), 8 rows per block ----------------
#define RROWS 8
__global__ void __launch_bounds__(512) k_res(float* __restrict__ out) {
    int b  = blockIdx.x >> 6;            // 0..7
    int y0 = (blockIdx.x & 63) * RROWS;  // base output row
    int tid = threadIdx.x;               // 0..511
    __shared__ float2 tmp[RROWS][32];    // [row][col] = (ch0, ch1)

    {                                    // H pass: 8 rows x 2 ch x 32 cols = 512 threads
        int row = tid >> 6, ch = (tid >> 5) & 1, xx = tid & 31;
        int y = y0 + row;
        float4 wa = g_rwp[y*2], wb = g_rwp[y*2+1];
        int j0 = __float_as_int(wb.z);
        float w[6] = {wa.x, wa.y, wa.z, wa.w, wb.x, wb.y};
        const float* q = g_qv + ((size_t)b * 2 + ch) * 1024 + xx;
        float s = 0.0f;
        #pragma unroll
        for (int k = 0; k < 6; k++) {
            int j = j0 + k; j = j < 0 ? 0 : (j > 31 ? 31 : j);
            s += w[k] * q[j * 32];
        }
        ((float*)&tmp[row][xx])[ch] = s;
    }
    __syncthreads();

    // W pass: weights + clamped indices depend only on x = tid -> compute once, reuse 8 rows
    float4 wa = g_rwp[tid*2], wb = g_rwp[tid*2+1];
    int j0 = __float_as_int(wb.z);
    float w[6] = {wa.x, wa.y, wa.z, wa.w, wb.x, wb.y};
    int jj[6];
    #pragma unroll
    for (int k = 0; k < 6; k++) {
        int j = j0 + k; jj[k] = j < 0 ? 0 : (j > 31 ? 31 : j);
    }

    float* o0p = out + (((size_t)b*2 + 0) * 512 + y0) * 512 + tid;
    float* o1p = out + (((size_t)b*2 + 1) * 512 + y0) * 512 + tid;
    #pragma unroll
    for (int row = 0; row < RROWS; row++) {
        float v0 = 0.0f, v1 = 0.0f;
        #pragma unroll
        for (int k = 0; k < 6; k++) {
            float2 tv = tmp[row][jj[k]];
            v0 = fmaf(w[k], tv.x, v0);
            v1 = fmaf(w[k], tv.y, v1);
        }
        float r0 = fminf(fmaxf(rintf(v0), 0.0f), 255.0f);
        float r1 = fminf(fmaxf(rintf(v1), 0.0f), 255.0f);
        float u0 = fmaf(2.0f, r0, -255.0f);
        float u1 = fmaf(2.0f, r1, -255.0f);
        float wn = rsqrtf(u0*u0 + u1*u1);
        o0p[row * 512] = u0 * wn;
        o1p[row * 512] = u1 * wn;
    }
}

extern "C" void kernel_launch(void* const* d_in, const int* in_sizes, int n_in,
                              void* d_out, int out_size) {
    (void)in_sizes; (void)n_in; (void)out_size;
    const float* x = (const float*)d_in[0];
    float* out = (float*)d_out;

    k_pre<<<dim3(16, 32, BATCH), dim3(32, 16)>>>(x);
    k_agg<<<dim3(32, 32, BATCH), AGT>>>();
    k_dom<<<64, 128>>>();
    k_res<<<BATCH * 64, 512>>>(out);
}

// round 15
// speedup vs baseline: 1.9662x; 1.0483x over previous
#include <cuda_runtime.h>
#include <cstdint>
#include <cstdlib>

#define HW    512
#define NPIX  (HW*HW)        // 262144 = 2^18
#define BATCH 8
#define NBINS 9
#define CELLS 32

static __device__ float2 g_pix [BATCH*NPIX];          // 16 MB: (w0 with slot in low 4 bits, w1)
static __device__ float  g_hog [BATCH*NBINS*CELLS*CELLS]; // bin-major: [b][k][cell]
static __device__ int    g_maxsq[BATCH];              // per-batch max cell sqnorm (float bits)
static __device__ float4 g_rwp [HW*2];                // packed lanczos weights: w0..w5, j0(bits), 0
static __device__ float  g_trig[27];                  // ss[9], cc[9], sc[9]

__device__ __forceinline__ float lanczos3(float x) {
    if (x > 3.0f) return 0.0f;
    if (x > 1e-3f) {
        float px = 3.1415927410125732f * x;
        float y  = (3.0f * sinf(px)) * sinf(px / 3.0f);
        return y / (9.8696044921875f * (x * x));
    }
    return 1.0f;
}

// fast atan2 folded into [0, pi]: o = mod(atan2(gy,gx)+pi, pi)
// cephes atanf core (deg-9 poly + tan(pi/8) reduction), ~1e-7 rad abs error.
__device__ __forceinline__ float fold_atan2(float gy, float gx) {
    float gxp = (gy < 0.0f) ? -gx : gx;
    float ay = fabsf(gy);
    float ax = fabsf(gxp);
    float mn = fminf(ax, ay), mx = fmaxf(ax, ay);
    float r = (mx > 0.0f) ? __fdividef(mn, mx) : 0.0f;   // [0,1]
    bool red = r > 0.4142135679721832f;                  // tan(pi/8)
    float t = red ? __fdividef(r - 1.0f, r + 1.0f) : r;  // [-0.414, 0.414]
    float z = t * t;
    float p = fmaf(fmaf(fmaf(8.05374449538e-2f, z, -1.38776856032e-1f), z,
                        1.99777106478e-1f), z, -3.33329491539e-1f);
    p = fmaf(p * z, t, t);
    if (red) p += 0.7853981633974483f;                   // + pi/4
    float a = (ay > ax) ? 1.5707963267948966f - p : p;
    if (gxp < 0.0f) a = 3.14159265358979323846f - a;
    if (ay == 0.0f) a = 0.0f;   // matches fmod(atan2(0,neg)+pi, pi) == 0
    return a;                    // [0, pi]
}

// ---------------- fused grayscale + gradient + 2-bin pack (+ table init in block 0) ----------------
__global__ void __launch_bounds__(512) k_pre(const float* __restrict__ x) {
    __shared__ float gs[18][34];
    int tx = threadIdx.x, ty = threadIdx.y;       // (32,16)
    int tid = ty * 32 + tx;
    int bx = blockIdx.x * 32, by = blockIdx.y * 16, b = blockIdx.z;
    const float* xb = x + (size_t)b * 3 * NPIX;

    #pragma unroll
    for (int i = tid; i < 18 * 34; i += 512) {
        int r = i / 34, c = i % 34;
        int gr = by + r - 1, gc = bx + c - 1;
        float v = 0.0f;
        if (gr >= 0 && gr < 512 && gc >= 0 && gc < 512) {
            int p = gr * 512 + gc;
            v = xb[p]*0.299f + xb[NPIX+p]*0.587f + xb[2*NPIX+p]*0.114f;
        }
        gs[r][c] = v;
    }

    // ---- table init, done once by block (0,0,0) (consumers all run in later kernels) ----
    if (blockIdx.x == 0 && blockIdx.y == 0 && blockIdx.z == 0) {
        int t = tid;
        if (t < 8) g_maxsq[t] = 0;
        if (t < HW) {
            float sample = (t + 0.5f) * 0.0625f - 0.5f;
            int j0 = (int)floorf(sample - 3.0f) + 1;
            float w[6]; float wsum = 0.0f;
            #pragma unroll
            for (int k = 0; k < 6; k++) {
                int j = j0 + k;
                float wt = 0.0f;
                if (j >= 0 && j < 32) wt = lanczos3(fabsf(sample - (float)j));
                w[k] = wt; wsum += wt;
            }
            float4 a, bb;
            a.x = w[0]/wsum; a.y = w[1]/wsum; a.z = w[2]/wsum; a.w = w[3]/wsum;
            bb.x = w[4]/wsum; bb.y = w[5]/wsum; bb.z = __int_as_float(j0); bb.w = 0.0f;
            g_rwp[t*2]   = a;
            g_rwp[t*2+1] = bb;
        }
        if (t < 9) {
            const float PI_F = 3.1415927410125732f;
            float cen = 10.0f + 20.0f * (float)t;
            float th  = (cen / 180.0f) * PI_F;
            float s = sinf(th), c = cosf(th);
            g_trig[t]      = s * s;
            g_trig[9 + t]  = c * c;
            g_trig[18 + t] = s * c;
        }
    }
    __syncthreads();

    float gx = gs[ty+1][tx+2] - gs[ty+1][tx];
    float gy = gs[ty+2][tx+1] - gs[ty][tx+1];
    float mag = sqrtf(gx*gx + gy*gy);
    float o = fold_atan2(gy, gx);                 // [0, pi]
    float orient = o * (180.0f / 3.14159265358979323846f);
    float f  = orient * 0.05f - 0.5f;
    float fb = floorf(f);
    int   b0 = (int)fb;                           // -1..8
    float frac = f - fb;
    float w0 = mag * (1.0f - frac);
    float w1 = mag * frac;
    unsigned u = (__float_as_uint(w0) & ~15u) | (unsigned)(b0 + 1);  // slot 0..9 in low bits
    float2 v;
    v.x = __uint_as_float(u);
    v.y = w1;
    g_pix[(size_t)b * NPIX + (by + ty) * 512 + (bx + tx)] = v;
}

// ---------------- HOG aggregation: one 96-thread block per output cell ----------------
// acc[s][t] float2: .x accumulates w0-contrib (bin s-1), .y accumulates w1-contrib (bin s).
// Row stride 96 float2 => 2*96*slot = 0 mod 32 banks: conflict-free for any slot.
// Each thread walks ~12 pixels of the 33x33 window (flat index t, t+96, ...).
#define AGT  96
#define ACC2 96
__global__ void __launch_bounds__(AGT) k_agg() {
    __shared__ __align__(16) float2 acc[10 * ACC2];
    __shared__ float2 rowsum[10];
    int t = threadIdx.x;             // 0..95
    int cx = blockIdx.x, cy = blockIdx.y, b = blockIdx.z;

    // init via float4: 10*ACC2 float2 = 5*ACC2 float4 = 480
    float4* ai = (float4*)acc;
    #pragma unroll
    for (int i = t; i < 5 * ACC2; i += AGT) ai[i] = make_float4(0.f, 0.f, 0.f, 0.f);

    int r0 = cy * 16 - 16, c0 = cx * 16 - 16;
    const float2* gp = g_pix + ((size_t)b << 18);
    const float invD = 1.0f / 22.627416997969522f;
    __syncthreads();

    float2* accb = acc + t;
    #pragma unroll
    for (int it = 0; it < 12; it++) {
        int i = t + it * AGT;
        if (it < 11 || i < 1089) {           // only last iter needs the guard
            int dy = i / 33;
            int dx = i - dy * 33;
            int r = abs(r0 + dy); if (r > 511) r = 1022 - r;
            int c = abs(c0 + dx); if (c > 511) c = 1022 - c;
            float2 p = gp[(r << 9) + c];
            int qy = dy - 16, qx = dx - 16;
            float dist = sqrtf((float)(qy*qy + qx*qx));
            float fv = fmaf(dist, -invD, 1.0f);
            int slot = __float_as_int(p.x) & 15;
            float2* ap = accb + slot * ACC2;
            float2 a = *ap;
            a.x = fmaf(fv, p.x, a.x);
            a.y = fmaf(fv, p.y, a.y);
            *ap = a;
        }
    }
    __syncthreads();

    // per-row float2 sums: warp w reduces rows w, w+3, w+6, w+9 (3 warps, 10 rows)
    {
        int w = t >> 5, lane = t & 31;
        for (int row = w; row < 10; row += 3) {
            const float2* rp = acc + row * ACC2;
            float2 s = make_float2(0.0f, 0.0f);
            #pragma unroll
            for (int j = 0; j < 3; j++) {
                float2 v = rp[lane + 32 * j];
                s.x += v.x; s.y += v.y;
            }
            #pragma unroll
            for (int o = 16; o > 0; o >>= 1) {
                s.x += __shfl_xor_sync(0xffffffffu, s.x, o);
                s.y += __shfl_xor_sync(0xffffffffu, s.y, o);
            }
            if (lane == 0) rowsum[row] = s;
        }
    }
    __syncthreads();

    // bin k = S[k+1].x + S[k].y  (warp 0 only); then 9-lane square-sum + atomicMax
    if (t < 32) {
        float bin = 0.0f;
        if (t < 9) {
            bin = rowsum[t + 1].x + rowsum[t].y;
            g_hog[(((size_t)b * 9 + t) << 10) + (cy << 5) + cx] = bin;
        }
        float sq = bin * bin;
        #pragma unroll
        for (int o = 16; o > 0; o >>= 1) sq += __shfl_xor_sync(0xffffffffu, sq, o);
        if (t == 0) atomicMax(&g_maxsq[b], __float_as_int(sq));  // sq>=0: int order == float order
    }
}

// ---------------- fused eigen+quantize + Lanczos resize (32x32 -> 512x512), 8 rows/block ----------------
// Stage 1: the <=7 qv rows this block needs are computed from g_hog directly (per-block redundant).
// Stage 2: H pass (8 rows x 2ch x 32 cols). Stage 3: W pass with per-x weights reused over 8 rows.
#define RROWS 8
__global__ void __launch_bounds__(512) k_res(float* __restrict__ out) {
    int b  = blockIdx.x >> 6;            // 0..7
    int y0 = (blockIdx.x & 63) * RROWS;  // base output row
    int tid = threadIdx.x;               // 0..511
    __shared__ float2 qvs[7][32];        // [local cell row][col] = (q0, q1)
    __shared__ float2 tmp[RROWS][32];    // [row][col] = (ch0, ch1)

    // cell-row range needed by rows y0..y0+7 (j0 varies by <=1 across the block)
    float sa = (y0 + 0.5f) * 0.0625f - 0.5f;
    float sb = (y0 + 7.5f) * 0.0625f - 0.5f;
    int j0a = (int)floorf(sa - 3.0f) + 1;
    int j0b = (int)floorf(sb - 3.0f) + 1;
    int rlo = max(0, j0a);
    int rhi = min(31, j0b + 5);
    int ncells = (rhi - rlo + 1) << 5;   // <= 7*32 = 224

    // Stage 1: eigen + quantize for the needed cells
    if (tid < ncells) {
        int cell = (rlo << 5) + tid;     // rows are consecutive: (rlo + tid/32)*32 + tid%32
        float inv = 1.0f / __int_as_float(g_maxsq[b]);    // 1/maxn^2
        float A = 0.0f, C = 0.0f, Bb = 0.0f;
        #pragma unroll
        for (int k = 0; k < 9; k++) {
            float v = g_hog[(((size_t)b * 9 + k) << 10) + cell];
            float h2 = v * v * inv;
            A  += g_trig[k]      * h2;
            C  += g_trig[9 + k]  * h2;
            Bb -= g_trig[18 + k] * h2;
        }
        float dd  = (A - C) * 0.5f;
        float lam = (A + C) * 0.5f + sqrtf(dd*dd + Bb*Bb);
        float la = lam - A, lc = lam - C;
        float n1 = Bb*Bb + la*la;
        float n2 = lc*lc + Bb*Bb;
        bool use1 = (n1 >= n2);
        float vx = use1 ? Bb : lc;
        float vy = use1 ? la : Bb;
        float nr = sqrtf(vx*vx + vy*vy) + 1e-9f;
        float q0 = floorf((vx / nr + 1.0f) / 2.0f * 255.0f);
        float q1 = floorf((vy / nr + 1.0f) / 2.0f * 255.0f);
        qvs[tid >> 5][tid & 31] = make_float2(q0, q1);
    }
    __syncthreads();

    // Stage 2: H pass (8 rows x 2 ch x 32 cols = 512 threads)
    {
        int row = tid >> 6, ch = (tid >> 5) & 1, xx = tid & 31;
        int y = y0 + row;
        float4 wa = g_rwp[y*2], wb = g_rwp[y*2+1];
        int j0 = __float_as_int(wb.z);
        float w[6] = {wa.x, wa.y, wa.z, wa.w, wb.x, wb.y};
        float s = 0.0f;
        #pragma unroll
        for (int k = 0; k < 6; k++) {
            int j = j0 + k; j = j < 0 ? 0 : (j > 31 ? 31 : j);
            s += w[k] * ((const float*)&qvs[j - rlo][xx])[ch];
        }
        __syncthreads();                 // qvs read before anything overwrites; also orders tmp
        ((float*)&tmp[row][xx])[ch] = s;
    }
    __syncthreads();

    // Stage 3: W pass — weights + clamped indices depend only on x = tid; reuse over 8 rows
    float4 wa = g_rwp[tid*2], wb = g_rwp[tid*2+1];
    int j0 = __float_as_int(wb.z);
    float w[6] = {wa.x, wa.y, wa.z, wa.w, wb.x, wb.y};
    int jj[6];
    #pragma unroll
    for (int k = 0; k < 6; k++) {
        int j = j0 + k; jj[k] = j < 0 ? 0 : (j > 31 ? 31 : j);
    }

    float* o0p = out + (((size_t)b*2 + 0) * 512 + y0) * 512 + tid;
    float* o1p = out + (((size_t)b*2 + 1) * 512 + y0) * 512 + tid;
    #pragma unroll
    for (int row = 0; row < RROWS; row++) {
        float v0 = 0.0f, v1 = 0.0f;
        #pragma unroll
        for (int k = 0; k < 6; k++) {
            float2 tv = tmp[row][jj[k]];
            v0 = fmaf(w[k], tv.x, v0);
            v1 = fmaf(w[k], tv.y, v1);
        }
        float r0 = fminf(fmaxf(rintf(v0), 0.0f), 255.0f);
        float r1 = fminf(fmaxf(rintf(v1), 0.0f), 255.0f);
        float u0 = fmaf(2.0f, r0, -255.0f);
        float u1 = fmaf(2.0f, r1, -255.0f);
        float wn = rsqrtf(u0*u0 + u1*u1);
        o0p[row * 512] = u0 * wn;
        o1p[row * 512] = u1 * wn;
    }
}

extern "C" void kernel_launch(void* const* d_in, const int* in_sizes, int n_in,
                              void* d_out, int out_size) {
    (void)in_sizes; (void)n_in; (void)out_size;
    const float* x = (const float*)d_in[0];
    float* out = (float*)d_out;

    k_pre<<<dim3(16, 32, BATCH), dim3(32, 16)>>>(x);
    k_agg<<<dim3(32, 32, BATCH), AGT>>>();
    k_res<<<BATCH * 64, 512>>>(out);
}

// round 17
// speedup vs baseline: 2.1954x; 1.1165x over previous
#include <cuda_runtime.h>
#include <cstdint>
#include <cstdlib>

#define HW    512
#define NPIX  (HW*HW)        // 262144 = 2^18
#define BATCH 8
#define NBINS 9
#define CELLS 32

static __device__ float2 g_pix [BATCH*NPIX];          // 16 MB: (w0 with slot in low 4 bits, w1)
static __device__ float  g_hog [BATCH*NBINS*CELLS*CELLS]; // bin-major: [b][k][cell]
static __device__ int    g_maxsq[BATCH];              // per-batch max cell sqnorm (float bits)
static __device__ float4 g_rwp [HW*2];                // packed lanczos weights: w0..w5, j0(bits), 0
static __device__ float  g_trig[27];                  // ss[9], cc[9], sc[9]

__device__ __forceinline__ float lanczos3(float x) {
    if (x > 3.0f) return 0.0f;
    if (x > 1e-3f) {
        float px = 3.1415927410125732f * x;
        float y  = (3.0f * sinf(px)) * sinf(px / 3.0f);
        return y / (9.8696044921875f * (x * x));
    }
    return 1.0f;
}

// fast atan2 folded into [0, pi]: o = mod(atan2(gy,gx)+pi, pi)
// cephes atanf core (deg-9 poly + tan(pi/8) reduction), ~1e-7 rad abs error.
__device__ __forceinline__ float fold_atan2(float gy, float gx) {
    float gxp = (gy < 0.0f) ? -gx : gx;
    float ay = fabsf(gy);
    float ax = fabsf(gxp);
    float mn = fminf(ax, ay), mx = fmaxf(ax, ay);
    float r = (mx > 0.0f) ? __fdividef(mn, mx) : 0.0f;   // [0,1]
    bool red = r > 0.4142135679721832f;                  // tan(pi/8)
    float t = red ? __fdividef(r - 1.0f, r + 1.0f) : r;  // [-0.414, 0.414]
    float z = t * t;
    float p = fmaf(fmaf(fmaf(8.05374449538e-2f, z, -1.38776856032e-1f), z,
                        1.99777106478e-1f), z, -3.33329491539e-1f);
    p = fmaf(p * z, t, t);
    if (red) p += 0.7853981633974483f;                   // + pi/4
    float a = (ay > ax) ? 1.5707963267948966f - p : p;
    if (gxp < 0.0f) a = 3.14159265358979323846f - a;
    if (ay == 0.0f) a = 0.0f;   // matches fmod(atan2(0,neg)+pi, pi) == 0
    return a;                    // [0, pi]
}

// ---------------- fused grayscale + gradient + 2-bin pack (+ table init in block 0) ----------------
// Tile 128x16 pixels per block, float4 halo loads (18 rows x 34 vec4), all vectors
// either fully inside or fully outside the image (halo cols are 4-aligned).
__global__ void __launch_bounds__(512) k_pre(const float* __restrict__ x) {
    __shared__ float gs[18][136];
    int tid = threadIdx.x;
    int bx = blockIdx.x * 128, by = blockIdx.y * 16, b = blockIdx.z;
    const float* xb = x + (size_t)b * 3 * NPIX;
    const float4* c0 = (const float4*)xb;
    const float4* c1 = (const float4*)(xb + NPIX);
    const float4* c2 = (const float4*)(xb + 2*NPIX);

    #pragma unroll
    for (int i = tid; i < 18 * 34; i += 512) {
        int r = i / 34, v = i - r * 34;
        int gr = by + r - 1;
        int gc = bx - 4 + (v << 2);            // 4-aligned vector col
        float4 g4 = make_float4(0.f, 0.f, 0.f, 0.f);
        if (gr >= 0 && gr < 512 && gc >= 0 && gc < 512) {
            int idx = (gr << 7) + (gc >> 2);   // (gr*512 + gc)/4
            float4 a = c0[idx], bb = c1[idx], cc = c2[idx];
            g4.x = a.x*0.299f + bb.x*0.587f + cc.x*0.114f;
            g4.y = a.y*0.299f + bb.y*0.587f + cc.y*0.114f;
            g4.z = a.z*0.299f + bb.z*0.587f + cc.z*0.114f;
            g4.w = a.w*0.299f + bb.w*0.587f + cc.w*0.114f;
        }
        *(float4*)&gs[r][v << 2] = g4;
    }

    // ---- table init, done once by block (0,0,0) (consumers all run in later kernels) ----
    if (blockIdx.x == 0 && blockIdx.y == 0 && blockIdx.z == 0) {
        int t = tid;
        if (t < 8) g_maxsq[t] = 0;
        if (t < HW) {
            float sample = (t + 0.5f) * 0.0625f - 0.5f;
            int j0 = (int)floorf(sample - 3.0f) + 1;
            float w[6]; float wsum = 0.0f;
            #pragma unroll
            for (int k = 0; k < 6; k++) {
                int j = j0 + k;
                float wt = 0.0f;
                if (j >= 0 && j < 32) wt = lanczos3(fabsf(sample - (float)j));
                w[k] = wt; wsum += wt;
            }
            float4 a, bb;
            a.x = w[0]/wsum; a.y = w[1]/wsum; a.z = w[2]/wsum; a.w = w[3]/wsum;
            bb.x = w[4]/wsum; bb.y = w[5]/wsum; bb.z = __int_as_float(j0); bb.w = 0.0f;
            g_rwp[t*2]   = a;
            g_rwp[t*2+1] = bb;
        }
        if (t < 9) {
            const float PI_F = 3.1415927410125732f;
            float cen = 10.0f + 20.0f * (float)t;
            float th  = (cen / 180.0f) * PI_F;
            float s = sinf(th), c = cosf(th);
            g_trig[t]      = s * s;
            g_trig[9 + t]  = c * c;
            g_trig[18 + t] = s * c;
        }
    }
    __syncthreads();

    // compute: each thread owns a 4-row column strip (col = tid&127, rows 4*(tid>>7)+0..3)
    int c  = tid & 127;
    int r0 = (tid >> 7) << 2;
    // vertical neighbors for gy: gs[r0 .. r0+5][c+4]
    float vcol[6];
    #pragma unroll
    for (int k = 0; k < 6; k++) vcol[k] = gs[r0 + k][c + 4];

    float2* op = &g_pix[((size_t)b << 18) + ((size_t)(by + r0) << 9) + bx + c];
    #pragma unroll
    for (int rr = 0; rr < 4; rr++) {
        float gx = gs[r0 + rr + 1][c + 5] - gs[r0 + rr + 1][c + 3];
        float gy = vcol[rr + 2] - vcol[rr];
        float mag = sqrtf(gx*gx + gy*gy);
        float o = fold_atan2(gy, gx);                 // [0, pi]
        float orient = o * (180.0f / 3.14159265358979323846f);
        float f  = orient * 0.05f - 0.5f;
        float fb = floorf(f);
        int   b0 = (int)fb;                           // -1..8
        float frac = f - fb;
        float w0 = mag * (1.0f - frac);
        float w1 = mag * frac;
        unsigned u = (__float_as_uint(w0) & ~15u) | (unsigned)(b0 + 1);  // slot 0..9
        float2 v;
        v.x = __uint_as_float(u);
        v.y = w1;
        op[(size_t)rr << 9] = v;
    }
}

// ---------------- HOG aggregation: one 96-thread block per output cell ----------------
// acc[s][t] float2: .x accumulates w0-contrib (bin s-1), .y accumulates w1-contrib (bin s).
// Row stride 96 float2 => 2*96*slot = 0 mod 32 banks: conflict-free for any slot.
// Each thread walks ~12 pixels of the 33x33 window (flat index t, t+96, ...).
#define AGT  96
#define ACC2 96
__global__ void __launch_bounds__(AGT) k_agg() {
    __shared__ __align__(16) float2 acc[10 * ACC2];
    __shared__ float2 rowsum[10];
    int t = threadIdx.x;             // 0..95
    int cx = blockIdx.x, cy = blockIdx.y, b = blockIdx.z;

    // init via float4: 10*ACC2 float2 = 5*ACC2 float4 = 480
    float4* ai = (float4*)acc;
    #pragma unroll
    for (int i = t; i < 5 * ACC2; i += AGT) ai[i] = make_float4(0.f, 0.f, 0.f, 0.f);

    int r0 = cy * 16 - 16, c0 = cx * 16 - 16;
    const float2* gp = g_pix + ((size_t)b << 18);
    const float invD = 1.0f / 22.627416997969522f;
    __syncthreads();

    float2* accb = acc + t;
    #pragma unroll
    for (int it = 0; it < 12; it++) {
        int i = t + it * AGT;
        if (it < 11 || i < 1089) {           // only last iter needs the guard
            int dy = i / 33;
            int dx = i - dy * 33;
            int r = abs(r0 + dy); if (r > 511) r = 1022 - r;
            int c = abs(c0 + dx); if (c > 511) c = 1022 - c;
            float2 p = gp[(r << 9) + c];
            int qy = dy - 16, qx = dx - 16;
            float dist = sqrtf((float)(qy*qy + qx*qx));
            float fv = fmaf(dist, -invD, 1.0f);
            int slot = __float_as_int(p.x) & 15;
            float2* ap = accb + slot * ACC2;
            float2 a = *ap;
            a.x = fmaf(fv, p.x, a.x);
            a.y = fmaf(fv, p.y, a.y);
            *ap = a;
        }
    }
    __syncthreads();

    // per-row float2 sums: warp w reduces rows w, w+3, w+6, w+9 (3 warps, 10 rows)
    {
        int w = t >> 5, lane = t & 31;
        for (int row = w; row < 10; row += 3) {
            const float2* rp = acc + row * ACC2;
            float2 s = make_float2(0.0f, 0.0f);
            #pragma unroll
            for (int j = 0; j < 3; j++) {
                float2 v = rp[lane + 32 * j];
                s.x += v.x; s.y += v.y;
            }
            #pragma unroll
            for (int o = 16; o > 0; o >>= 1) {
                s.x += __shfl_xor_sync(0xffffffffu, s.x, o);
                s.y += __shfl_xor_sync(0xffffffffu, s.y, o);
            }
            if (lane == 0) rowsum[row] = s;
        }
    }
    __syncthreads();

    // bin k = S[k+1].x + S[k].y  (warp 0 only); then 9-lane square-sum + atomicMax
    if (t < 32) {
        float bin = 0.0f;
        if (t < 9) {
            bin = rowsum[t + 1].x + rowsum[t].y;
            g_hog[(((size_t)b * 9 + t) << 10) + (cy << 5) + cx] = bin;
        }
        float sq = bin * bin;
        #pragma unroll
        for (int o = 16; o > 0; o >>= 1) sq += __shfl_xor_sync(0xffffffffu, sq, o);
        if (t == 0) atomicMax(&g_maxsq[b], __float_as_int(sq));  // sq>=0: int order == float order
    }
}

// ---------------- fused eigen+quantize + Lanczos resize (32x32 -> 512x512), 8 rows/block ----------------
#define RROWS 8
__global__ void __launch_bounds__(512) k_res(float* __restrict__ out) {
    int b  = blockIdx.x >> 6;            // 0..7
    int y0 = (blockIdx.x & 63) * RROWS;  // base output row
    int tid = threadIdx.x;               // 0..511
    __shared__ float2 qvs[7][32];        // [local cell row][col] = (q0, q1)
    __shared__ float2 tmp[RROWS][32];    // [row][col] = (ch0, ch1)

    // cell-row range needed by rows y0..y0+7 (j0 varies by <=1 across the block)
    float sa = (y0 + 0.5f) * 0.0625f - 0.5f;
    float sb = (y0 + 7.5f) * 0.0625f - 0.5f;
    int j0a = (int)floorf(sa - 3.0f) + 1;
    int j0b = (int)floorf(sb - 3.0f) + 1;
    int rlo = max(0, j0a);
    int rhi = min(31, j0b + 5);
    int ncells = (rhi - rlo + 1) << 5;   // <= 7*32 = 224

    // Stage 1: eigen + quantize for the needed cells
    if (tid < ncells) {
        int cell = (rlo << 5) + tid;
        float inv = 1.0f / __int_as_float(g_maxsq[b]);    // 1/maxn^2
        float A = 0.0f, C = 0.0f, Bb = 0.0f;
        #pragma unroll
        for (int k = 0; k < 9; k++) {
            float v = g_hog[(((size_t)b * 9 + k) << 10) + cell];
            float h2 = v * v * inv;
            A  += g_trig[k]      * h2;
            C  += g_trig[9 + k]  * h2;
            Bb -= g_trig[18 + k] * h2;
        }
        float dd  = (A - C) * 0.5f;
        float lam = (A + C) * 0.5f + sqrtf(dd*dd + Bb*Bb);
        float la = lam - A, lc = lam - C;
        float n1 = Bb*Bb + la*la;
        float n2 = lc*lc + Bb*Bb;
        bool use1 = (n1 >= n2);
        float vx = use1 ? Bb : lc;
        float vy = use1 ? la : Bb;
        float nr = sqrtf(vx*vx + vy*vy) + 1e-9f;
        float q0 = floorf((vx / nr + 1.0f) / 2.0f * 255.0f);
        float q1 = floorf((vy / nr + 1.0f) / 2.0f * 255.0f);
        qvs[tid >> 5][tid & 31] = make_float2(q0, q1);
    }
    __syncthreads();

    // Stage 2: H pass (8 rows x 2 ch x 32 cols = 512 threads)
    {
        int row = tid >> 6, ch = (tid >> 5) & 1, xx = tid & 31;
        int y = y0 + row;
        float4 wa = g_rwp[y*2], wb = g_rwp[y*2+1];
        int j0 = __float_as_int(wb.z);
        float w[6] = {wa.x, wa.y, wa.z, wa.w, wb.x, wb.y};
        float s = 0.0f;
        #pragma unroll
        for (int k = 0; k < 6; k++) {
            int j = j0 + k; j = j < 0 ? 0 : (j > 31 ? 31 : j);
            s += w[k] * ((const float*)&qvs[j - rlo][xx])[ch];
        }
        __syncthreads();
        ((float*)&tmp[row][xx])[ch] = s;
    }
    __syncthreads();

    // Stage 3: W pass — weights + clamped indices depend only on x = tid; reuse over 8 rows
    float4 wa = g_rwp[tid*2], wb = g_rwp[tid*2+1];
    int j0 = __float_as_int(wb.z);
    float w[6] = {wa.x, wa.y, wa.z, wa.w, wb.x, wb.y};
    int jj[6];
    #pragma unroll
    for (int k = 0; k < 6; k++) {
        int j = j0 + k; jj[k] = j < 0 ? 0 : (j > 31 ? 31 : j);
    }

    float* o0p = out + (((size_t)b*2 + 0) * 512 + y0) * 512 + tid;
    float* o1p = out + (((size_t)b*2 + 1) * 512 + y0) * 512 + tid;
    #pragma unroll
    for (int row = 0; row < RROWS; row++) {
        float v0 = 0.0f, v1 = 0.0f;
        #pragma unroll
        for (int k = 0; k < 6; k++) {
            float2 tv = tmp[row][jj[k]];
            v0 = fmaf(w[k], tv.x, v0);
            v1 = fmaf(w[k], tv.y, v1);
        }
        float r0 = fminf(fmaxf(rintf(v0), 0.0f), 255.0f);
        float r1 = fminf(fmaxf(rintf(v1), 0.0f), 255.0f);
        float u0 = fmaf(2.0f, r0, -255.0f);
        float u1 = fmaf(2.0f, r1, -255.0f);
        float wn = rsqrtf(u0*u0 + u1*u1);
        o0p[row * 512] = u0 * wn;
        o1p[row * 512] = u1 * wn;
    }
}

extern "C" void kernel_launch(void* const* d_in, const int* in_sizes, int n_in,
                              void* d_out, int out_size) {
    (void)in_sizes; (void)n_in; (void)out_size;
    const float* x = (const float*)d_in[0];
    float* out = (float*)d_out;

    k_pre<<<dim3(4, 32, BATCH), 512>>>(x);
    k_agg<<<dim3(32, 32, BATCH), AGT>>>();
    k_res<<<BATCH * 64, 512>>>(out);
}